// round 9
// baseline (speedup 1.0000x reference)
#include <cuda_runtime.h>
#include <cuda_bf16.h>
#include <cstdint>

#define PL (512*512)
typedef unsigned long long u64;
typedef __nv_bfloat16 bf16;

// ---------------- scratch ----------------
__device__ float g_t[8][4][16][2];
__device__ float g_scal[3];
__device__ float g_part[8][512][2];
__device__ float g_stats[8][2];
__device__ float g_mi[8][2][16][512];
__device__ float g_mj[8][2][16][512];
__device__ float g_mod[8][2][PL];
__device__ bf16 g_A0[2][512 * 1024];      // Wi^T pack: [hi/lo][m'][k2 = m | 512+m]
__device__ bf16 g_B0[2][8][1024 * 1024];  // wd0 block matrix: [hi/lo][b][row][k2]
__device__ bf16 g_A1[2][8][512 * 1024];   // stage-0 output: [hi/lo][b][m'][k2' = n | 512+n]
__device__ bf16 g_B1[2][1024 * 1024];     // Wj block matrix, rows 2n' (r) / 2n'+1 (i)

#define SWZ(x)   ((x) ^ (((x) >> 3) & 0x70))   // 128B-row swizzle (pack kernels)
#define SWZ64(x) ((x) ^ (((x) >> 3) & 0x30))   // 64B-row swizzle (GEMM smem)

__device__ __forceinline__ uint32_t smem_u32(const void* p) {
    uint32_t a;
    asm("{ .reg .u64 t; cvta.to.shared.u64 t, %1; cvt.u32.u64 %0, t; }" : "=r"(a) : "l"(p));
    return a;
}
__device__ __forceinline__ void split2(float v0, float v1, uint32_t& hi, uint32_t& lo) {
    __nv_bfloat162 h = __floats2bfloat162_rn(v0, v1);
    hi = *(uint32_t*)&h;
    float r0 = v0 - __bfloat162float(__low2bfloat16(h));
    float r1 = v1 - __bfloat162float(__high2bfloat16(h));
    __nv_bfloat162 l = __floats2bfloat162_rn(r0, r1);
    lo = *(uint32_t*)&l;
}
#define LDSM_X4(r0, r1, r2, r3, a) \
    asm volatile("ldmatrix.sync.aligned.m8n8.x4.shared.b16 {%0,%1,%2,%3}, [%4];" \
        : "=r"(r0), "=r"(r1), "=r"(r2), "=r"(r3) : "r"(a))
#define MMA16816(c, a, b) \
    asm volatile("mma.sync.aligned.m16n8k16.row.col.f32.bf16.bf16.f32 " \
        "{%0,%1,%2,%3}, {%4,%5,%6,%7}, {%8,%9}, {%0,%1,%2,%3};" \
        : "+f"((c)[0]), "+f"((c)[1]), "+f"((c)[2]), "+f"((c)[3]) \
        : "r"((a)[0]), "r"((a)[1]), "r"((a)[2]), "r"((a)[3]), "r"((b)[0]), "r"((b)[1]))
#define CP_ASYNC16(s, g) \
    asm volatile("cp.async.cg.shared.global [%0], [%1], 16;" :: "r"(s), "l"(g) : "memory")
#define CP_COMMIT()  asm volatile("cp.async.commit_group;" ::: "memory")
#define CP_WAIT(n)   asm volatile("cp.async.wait_group %0;" :: "n"(n) : "memory")

// ---------------- k_setup ----------------
__global__ void k_setup(const float* __restrict__ x, const float* __restrict__ mt,
                        const float* __restrict__ td, const float* __restrict__ rd) {
    int tid = threadIdx.x;
    for (int o = tid; o < 1024; o += 256) {
        int e = o & 1, c2 = (o >> 1) & 15, k = (o >> 5) & 3, b = o >> 7;
        float s = 0.f;
        #pragma unroll
        for (int c = 0; c < 16; ++c)
            s += x[b * 16 + c] * mt[(k * 16 + c) * 32 + c2 * 2 + e];
        g_t[b][k][c2][e] = s;
    }
    if (tid == 0) {
        float A = 0.f, Bv = 0.f, K = 0.f;
        for (int c = 0; c < 16; ++c) {
            float rr = rd[2 * c], ri = rd[2 * c + 1];
            float tr = td[2 * c], ti = td[2 * c + 1];
            A += ri; Bv -= rr; K += ti * ri - tr * rr;
        }
        g_scal[0] = A; g_scal[1] = Bv; g_scal[2] = K;
    }
}

// ---------------- k_mimj ----------------
__global__ void k_mimj(const float* __restrict__ mod_i, const float* __restrict__ mod_j,
                       const float* __restrict__ inv) {
    int b = blockIdx.x >> 4, r = blockIdx.x & 15, m = threadIdx.x;
    __shared__ float st[16][8];
    __shared__ float siv[16][2];
    if (m < 128) st[m >> 3][m & 7] = g_t[b][(m & 7) >> 1][m >> 3][m & 1];
    if (m < 32)  siv[m >> 1][m & 1] = inv[m];
    __syncthreads();

    float sir = 0.f, sii = 0.f, sjr = 0.f, sji = 0.f;
    #pragma unroll 4
    for (int c = 0; c < 16; ++c) {
        float t0r = st[c][0], t0i = st[c][1], t1r = st[c][2], t1i = st[c][3];
        float t2r = st[c][4], t2i = st[c][5], t3r = st[c][6], t3i = st[c][7];
        float ivr = siv[c][0], ivi = siv[c][1];
        float2 vi = ((const float2*)mod_i)[(c * 16 + r) * 512 + m];
        float ar = vi.x + t0r, ai = vi.y + t0i;
        float r1 = ai * t1i - ar * t1r;
        float i1 = ar * t1i + ai * t1r;
        sir += i1 * ivi - r1 * ivr;
        sii += r1 * ivi + i1 * ivr;
        float2 vj = ((const float2*)mod_j)[(c * 16 + r) * 512 + m];
        float br2 = vj.x + t2r, bi2 = vj.y + t2i;
        float r2 = bi2 * t3i - br2 * t3r;
        float i2 = br2 * t3i + bi2 * t3r;
        float idn = 1.f / (r2 * r2 + i2 * i2);
        sjr += (ivr * r2 + ivi * i2) * idn;
        sji += (ivr * i2 - ivi * r2) * idn;
    }
    g_mi[b][0][r][m] = sir; g_mi[b][1][r][m] = sii;
    g_mj[b][0][r][m] = sjr; g_mj[b][1][r][m] = sji;
}

// ---------------- k_mod ----------------
__global__ void k_mod() {
    int b = blockIdx.x >> 9, m = blockIdx.x & 511;
    int tid = threadIdx.x;
    __shared__ float smi[2][16];
    if (tid < 32) smi[tid >> 4][tid & 15] = g_mi[b][tid >> 4][tid & 15][m];
    __syncthreads();
    float s1 = 0.f, s2 = 0.f;
    #pragma unroll
    for (int q = 0; q < 4; ++q) {
        int n = tid + q * 128;
        float cr = 0.f, ci = 0.f;
        #pragma unroll
        for (int r = 0; r < 16; ++r) {
            float air = smi[0][r], aii = smi[1][r];
            float bjr = g_mj[b][0][r][n], bji = g_mj[b][1][r][n];
            cr += air * bjr - aii * bji;
            ci += air * bji + aii * bjr;
        }
        g_mod[b][0][m * 512 + n] = cr;
        g_mod[b][1][m * 512 + n] = ci;
        s1 += cr; s2 += cr * cr;
    }
    __shared__ float rs1[128], rs2[128];
    rs1[tid] = s1; rs2[tid] = s2; __syncthreads();
    for (int off = 64; off; off >>= 1) {
        if (tid < off) { rs1[tid] += rs1[tid + off]; rs2[tid] += rs2[tid + off]; }
        __syncthreads();
    }
    if (tid == 0) { g_part[b][m][0] = rs1[0]; g_part[b][m][1] = rs2[0]; }
}

// ---------------- k_stats ----------------
__global__ void k_stats() {
    int b = blockIdx.x, t = threadIdx.x;
    __shared__ float r1[256], r2[256];
    r1[t] = g_part[b][t][0] + g_part[b][t + 256][0];
    r2[t] = g_part[b][t][1] + g_part[b][t + 256][1];
    __syncthreads();
    for (int off = 128; off; off >>= 1) {
        if (t < off) { r1[t] += r1[t + off]; r2[t] += r2[t + off]; }
        __syncthreads();
    }
    if (t == 0) { g_stats[b][0] = r1[0]; g_stats[b][1] = r2[0]; }
}

// ---------------- k_packA0 ----------------
__global__ void k_packA0(const float* __restrict__ Wi) {
    int mt = blockIdx.x * 32, pt = blockIdx.y * 32;
    __shared__ float sr[32][33], si[32][33];
    int t = threadIdx.x;
    #pragma unroll
    for (int rr = 0; rr < 4; ++rr) {
        int e = t + 256 * rr, ml = e >> 5, pl = e & 31;
        float2 v = ((const float2*)Wi)[(mt + ml) * 512 + pt + pl];
        sr[ml][pl] = v.x; si[ml][pl] = v.y;
    }
    __syncthreads();
    int pl = t >> 3, m4 = (t & 7) * 4;
    uint32_t hr[2], lr[2], hi_[2], li_[2];
    #pragma unroll
    for (int g = 0; g < 2; ++g) {
        split2(sr[m4 + 2 * g][pl], sr[m4 + 2 * g + 1][pl], hr[g], lr[g]);
        split2(si[m4 + 2 * g][pl], si[m4 + 2 * g + 1][pl], hi_[g], li_[g]);
    }
    size_t row = (size_t)(pt + pl) * 1024;
    int col = mt + m4;
    *(uint2*)(g_A0[0] + row + col)       = make_uint2(hr[0], hr[1]);
    *(uint2*)(g_A0[1] + row + col)       = make_uint2(lr[0], lr[1]);
    *(uint2*)(g_A0[0] + row + 512 + col) = make_uint2(hi_[0], hi_[1]);
    *(uint2*)(g_A0[1] + row + 512 + col) = make_uint2(li_[0], li_[1]);
}

// ---------------- k_packB1 ----------------
__global__ void k_packB1(const float* __restrict__ Wj) {
    int nt = blockIdx.x * 32, pt = blockIdx.y * 32;
    __shared__ float sr[32][33], si[32][33];
    int t = threadIdx.x;
    #pragma unroll
    for (int rr = 0; rr < 4; ++rr) {
        int e = t + 256 * rr, nl = e >> 5, pl = e & 31;
        float2 v = ((const float2*)Wj)[(nt + nl) * 512 + pt + pl];
        sr[nl][pl] = v.x; si[nl][pl] = v.y;
    }
    __syncthreads();
    int pl = t >> 3, m4 = (t & 7) * 4;
    uint32_t hr[2], lr[2], hi_[2], li_[2];
    #pragma unroll
    for (int g = 0; g < 2; ++g) {
        split2(sr[m4 + 2 * g][pl], sr[m4 + 2 * g + 1][pl], hr[g], lr[g]);
        split2(si[m4 + 2 * g][pl], si[m4 + 2 * g + 1][pl], hi_[g], li_[g]);
    }
    int np = pt + pl;
    size_t row_r = (size_t)(2 * np) * 1024;
    size_t row_i = (size_t)(2 * np + 1) * 1024;
    int col = nt + m4;
    *(uint2*)(g_B1[0] + row_r + col)       = make_uint2(hr[0], hr[1]);
    *(uint2*)(g_B1[1] + row_r + col)       = make_uint2(lr[0], lr[1]);
    *(uint2*)(g_B1[0] + row_r + 512 + col) = make_uint2(hi_[0] ^ 0x80008000u, hi_[1] ^ 0x80008000u);
    *(uint2*)(g_B1[1] + row_r + 512 + col) = make_uint2(li_[0] ^ 0x80008000u, li_[1] ^ 0x80008000u);
    *(uint2*)(g_B1[0] + row_i + col)       = make_uint2(hi_[0], hi_[1]);
    *(uint2*)(g_B1[1] + row_i + col)       = make_uint2(li_[0], li_[1]);
    *(uint2*)(g_B1[0] + row_i + 512 + col) = make_uint2(hr[0], hr[1]);
    *(uint2*)(g_B1[1] + row_i + 512 + col) = make_uint2(lr[0], lr[1]);
}

// ---------------- k_packB0 ----------------
__global__ void k_packB0(const float* __restrict__ wb) {
    int mt = blockIdx.x * 32, nt = blockIdx.y * 32, b = blockIdx.z;
    float s1 = g_stats[b][0], s2 = g_stats[b][1];
    float mean = s1 * (1.f / 262144.f);
    float var = (s2 - s1 * mean) * (1.f / 262143.f);
    float istd = rsqrtf(var);
    __shared__ float wr[32][33], wi[32][33];
    int t = threadIdx.x;
    #pragma unroll
    for (int rr = 0; rr < 4; ++rr) {
        int e = t + 256 * rr, ml = e >> 5, nl = e & 31;
        int idx = (mt + ml) * 512 + nt + nl;
        float2 w = ((const float2*)wb)[idx];
        wr[ml][nl] = w.x * (1.f + (g_mod[b][0][idx] - mean) * istd);
        wi[ml][nl] = w.y * (1.f + g_mod[b][1][idx]);
    }
    __syncthreads();
    int nl = t >> 3, m4 = (t & 7) * 4;
    uint32_t hr[2], lr[2], hi_[2], li_[2];
    #pragma unroll
    for (int g = 0; g < 2; ++g) {
        split2(wr[m4 + 2 * g][nl], wr[m4 + 2 * g + 1][nl], hr[g], lr[g]);
        split2(wi[m4 + 2 * g][nl], wi[m4 + 2 * g + 1][nl], hi_[g], li_[g]);
    }
    size_t row_r = (size_t)(nt + nl) * 1024;
    size_t row_i = (size_t)(512 + nt + nl) * 1024;
    int col = mt + m4;
    bf16* Bh = g_B0[0][b]; bf16* Bl = g_B0[1][b];
    *(uint2*)(Bh + row_r + col)       = make_uint2(hr[0], hr[1]);
    *(uint2*)(Bl + row_r + col)       = make_uint2(lr[0], lr[1]);
    *(uint2*)(Bh + row_r + 512 + col) = make_uint2(hi_[0] ^ 0x80008000u, hi_[1] ^ 0x80008000u);
    *(uint2*)(Bl + row_r + 512 + col) = make_uint2(li_[0] ^ 0x80008000u, li_[1] ^ 0x80008000u);
    *(uint2*)(Bh + row_i + col)       = make_uint2(hi_[0], hi_[1]);
    *(uint2*)(Bl + row_i + col)       = make_uint2(li_[0], li_[1]);
    *(uint2*)(Bh + row_i + 512 + col) = make_uint2(hr[0], hr[1]);
    *(uint2*)(Bl + row_i + 512 + col) = make_uint2(lr[0], lr[1]);
}

// ---------------- mma.sync GEMM: K-chunk 32, 64B rows, 3-stage cp.async, 2 CTAs/SM ----
// buffer (32KB): Ahi @0, Alo @8K, Bhi @16K, Blo @24K. rows: 128 x 64B, SWZ64.
__device__ __forceinline__ void prefetch_chunk(
    const bf16* __restrict__ Ah, const bf16* __restrict__ Al,
    const bf16* __restrict__ Bh, const bf16* __restrict__ Bl,
    int arow, int brow, int kb, uint32_t sdst, int tid) {
    const bf16* srcs[4] = { Ah, Al, Bh, Bl };
    const int rows0[4] = { arow, arow, brow, brow };
    #pragma unroll
    for (int arr = 0; arr < 4; ++arr) {
        #pragma unroll
        for (int i = 0; i < 2; ++i) {
            int u = tid + 256 * i, row = u >> 2, seg = u & 3;
            const bf16* g = srcs[arr] + (size_t)(rows0[arr] + row) * 1024 + kb + seg * 8;
            uint32_t s = sdst + arr * 8192 + SWZ64(row * 64 + seg * 16);
            CP_ASYNC16(s, g);
        }
    }
    CP_COMMIT();
}

template<int STAGE>
__global__ void __launch_bounds__(256, 2) k_mma(float* __restrict__ gout) {
    extern __shared__ __align__(1024) char smem[];
    const int tid = threadIdx.x, wid = tid >> 5, lane = tid & 31;
    const int wm = wid >> 1, wn = wid & 1;
    const int b = blockIdx.z, My = blockIdx.y, Nx = blockIdx.x;
    const bf16 *Ahi, *Alo, *Bhi, *Blo;
    if (STAGE == 0) { Ahi = g_A0[0];    Alo = g_A0[1];    Bhi = g_B0[0][b]; Blo = g_B0[1][b]; }
    else            { Ahi = g_A1[0][b]; Alo = g_A1[1][b]; Bhi = g_B1[0];    Blo = g_B1[1]; }
    const int arow = My * 128, brow = Nx * 128;
    const uint32_t sb = smem_u32(smem);

    float c[2][8][4];
    #pragma unroll
    for (int mt = 0; mt < 2; ++mt)
        #pragma unroll
        for (int nt = 0; nt < 8; ++nt)
            #pragma unroll
            for (int q = 0; q < 4; ++q) c[mt][nt][q] = 0.f;

    prefetch_chunk(Ahi, Alo, Bhi, Blo, arow, brow, 0, sb, tid);
    prefetch_chunk(Ahi, Alo, Bhi, Blo, arow, brow, 32, sb + 32768, tid);

    for (int ch = 0; ch < 32; ++ch) {
        if (ch + 2 < 32)
            prefetch_chunk(Ahi, Alo, Bhi, Blo, arow, brow, (ch + 2) * 32,
                           sb + ((ch + 2) % 3) * 32768, tid);
        else
            CP_COMMIT();
        CP_WAIT(2);
        __syncthreads();

        const uint32_t sbuf = sb + (ch % 3) * 32768;
        const uint32_t sA = sbuf, sAl = sbuf + 8192, sB = sbuf + 16384, sBl = sbuf + 24576;
        #pragma unroll
        for (int ks = 0; ks < 2; ++ks) {
            uint32_t ah[2][4], al[2][4], bh[8][2], bl[8][2];
            #pragma unroll
            for (int mt = 0; mt < 2; ++mt) {
                int row = wm * 32 + mt * 16 + (lane & 15);
                uint32_t off = SWZ64(row * 64 + ks * 32 + (lane >> 4) * 16);
                LDSM_X4(ah[mt][0], ah[mt][1], ah[mt][2], ah[mt][3], sA + off);
                LDSM_X4(al[mt][0], al[mt][1], al[mt][2], al[mt][3], sAl + off);
            }
            #pragma unroll
            for (int ntp = 0; ntp < 4; ++ntp) {
                int row = wn * 64 + ntp * 16 + (lane >> 4) * 8 + (lane & 7);
                uint32_t off = SWZ64(row * 64 + ks * 32 + ((lane >> 3) & 1) * 16);
                LDSM_X4(bh[2 * ntp][0], bh[2 * ntp][1], bh[2 * ntp + 1][0], bh[2 * ntp + 1][1], sB + off);
                LDSM_X4(bl[2 * ntp][0], bl[2 * ntp][1], bl[2 * ntp + 1][0], bl[2 * ntp + 1][1], sBl + off);
            }
            #pragma unroll
            for (int mt = 0; mt < 2; ++mt)
                #pragma unroll
                for (int nt = 0; nt < 8; ++nt) {
                    MMA16816(c[mt][nt], ah[mt], bh[nt]);
                    MMA16816(c[mt][nt], al[mt], bh[nt]);
                    MMA16816(c[mt][nt], ah[mt], bl[nt]);
                }
        }
        __syncthreads();
    }

    // ---------------- epilogue (unchanged from verified R8) ----------------
    const int r0 = My * 128 + wm * 32 + (lane >> 2);
    if (STAGE == 0) {
        bf16* dh = g_A1[0][b]; bf16* dl = g_A1[1][b];
        #pragma unroll
        for (int mt = 0; mt < 2; ++mt)
            #pragma unroll
            for (int nt = 0; nt < 8; ++nt) {
                int row = r0 + mt * 16;
                int col = Nx * 128 + wn * 64 + nt * 8 + 2 * (lane & 3);
                uint32_t h, l;
                split2(c[mt][nt][0], c[mt][nt][1], h, l);
                *(uint32_t*)(dh + (size_t)row * 1024 + col) = h;
                *(uint32_t*)(dl + (size_t)row * 1024 + col) = l;
                split2(c[mt][nt][2], c[mt][nt][3], h, l);
                *(uint32_t*)(dh + (size_t)(row + 8) * 1024 + col) = h;
                *(uint32_t*)(dl + (size_t)(row + 8) * 1024 + col) = l;
            }
    } else {
        const float A_ = g_scal[0], B_ = g_scal[1], K_ = g_scal[2];
        float* O = gout + b * PL;
        #pragma unroll
        for (int mt = 0; mt < 2; ++mt)
            #pragma unroll
            for (int nt = 0; nt < 8; ++nt) {
                int row = r0 + mt * 16;
                int np = Nx * 64 + wn * 32 + nt * 4 + (lane & 3);
                O[(size_t)row * 512 + np] =
                    fmaf(c[mt][nt][1], A_, fmaf(c[mt][nt][0], B_, K_));
                O[(size_t)(row + 8) * 512 + np] =
                    fmaf(c[mt][nt][3], A_, fmaf(c[mt][nt][2], B_, K_));
            }
    }
}

// ---------------- launch ----------------
extern "C" void kernel_launch(void* const* d_in, const int* in_sizes, int n_in,
                              void* d_out, int out_size) {
    (void)in_sizes; (void)n_in; (void)out_size;
    const float* x   = (const float*)d_in[0];
    const float* Wi  = (const float*)d_in[1];
    const float* Wj  = (const float*)d_in[2];
    const float* Wb  = (const float*)d_in[3];
    const float* td  = (const float*)d_in[6];
    const float* rd  = (const float*)d_in[7];
    const float* mi  = (const float*)d_in[8];
    const float* mj  = (const float*)d_in[9];
    const float* inv = (const float*)d_in[10];
    const float* mt  = (const float*)d_in[11];
    float* out = (float*)d_out;

    const int SMEM_SZ = 3 * 32768;   // 96 KB
    cudaFuncSetAttribute(k_mma<0>, cudaFuncAttributeMaxDynamicSharedMemorySize, SMEM_SZ);
    cudaFuncSetAttribute(k_mma<1>, cudaFuncAttributeMaxDynamicSharedMemorySize, SMEM_SZ);

    k_setup<<<1, 256>>>(x, mt, td, rd);
    k_mimj<<<128, 512>>>(mi, mj, inv);
    k_mod<<<4096, 128>>>();
    k_stats<<<8, 256>>>();
    k_packA0<<<dim3(16, 16), 256>>>(Wi);
    k_packB1<<<dim3(16, 16), 256>>>(Wj);
    k_packB0<<<dim3(16, 16, 8), 256>>>(Wb);
    dim3 grid(8, 4, 8);
    k_mma<0><<<grid, 256, SMEM_SZ>>>(nullptr);
    k_mma<1><<<grid, 256, SMEM_SZ>>>(out);
}

// round 11
// speedup vs baseline: 1.4633x; 1.4633x over previous
#include <cuda_runtime.h>
#include <cuda_fp16.h>
#include <cstdint>

#define PL (512*512)
typedef unsigned long long u64;

// ---------------- scratch ----------------
__device__ float g_t[8][4][16][2];
__device__ float g_scal[3];
__device__ float g_part[8][512][2];
__device__ float g_stats[8][2];
__device__ float g_mi[8][2][16][512];
__device__ float g_mj[8][2][16][512];
__device__ float g_mod[8][2][PL];
__device__ half g_A0h[512 * 1024], g_A0l[512 * 1024];   // Wi^T pack: [m'][k2 = m | 512+m]
__device__ half g_B0h[8][1024 * 1024];                  // wd0 block matrix (hi only)
__device__ half g_A1h[8][512 * 1024], g_A1l[8][512 * 1024]; // stage-0 out: [m'][k2' = n | 512+n]
__device__ half g_B1h[1024 * 1024];                     // Wj block matrix, rows 2n'/2n'+1 (hi only)

#define SWZ(x) ((x) ^ (((x) >> 3) & 0x70))

__device__ __forceinline__ uint32_t smem_u32(const void* p) {
    uint32_t a;
    asm("{ .reg .u64 t; cvta.to.shared.u64 t, %1; cvt.u32.u64 %0, t; }" : "=r"(a) : "l"(p));
    return a;
}
// fp16 hi/lo split of a float pair
__device__ __forceinline__ void split2h(float v0, float v1, uint32_t& hi, uint32_t& lo) {
    __half2 h = __floats2half2_rn(v0, v1);
    hi = *(uint32_t*)&h;
    float r0 = v0 - __half2float(__low2half(h));
    float r1 = v1 - __half2float(__high2half(h));
    __half2 l = __floats2half2_rn(r0, r1);
    lo = *(uint32_t*)&l;
}
__device__ __forceinline__ uint32_t h2_rn(float v0, float v1) {
    __half2 h = __floats2half2_rn(v0, v1);
    return *(uint32_t*)&h;
}
#define LDSM_X4(r0, r1, r2, r3, a) \
    asm volatile("ldmatrix.sync.aligned.m8n8.x4.shared.b16 {%0,%1,%2,%3}, [%4];" \
        : "=r"(r0), "=r"(r1), "=r"(r2), "=r"(r3) : "r"(a))
#define MMA16816(c, a, b) \
    asm volatile("mma.sync.aligned.m16n8k16.row.col.f32.f16.f16.f32 " \
        "{%0,%1,%2,%3}, {%4,%5,%6,%7}, {%8,%9}, {%0,%1,%2,%3};" \
        : "+f"((c)[0]), "+f"((c)[1]), "+f"((c)[2]), "+f"((c)[3]) \
        : "r"((a)[0]), "r"((a)[1]), "r"((a)[2]), "r"((a)[3]), "r"((b)[0]), "r"((b)[1]))
#define CP_ASYNC16(s, g) \
    asm volatile("cp.async.cg.shared.global [%0], [%1], 16;" :: "r"(s), "l"(g) : "memory")
#define CP_COMMIT()  asm volatile("cp.async.commit_group;" ::: "memory")
#define CP_WAIT(n)   asm volatile("cp.async.wait_group %0;" :: "n"(n) : "memory")

// ---------------- k_setup ----------------
__global__ void k_setup(const float* __restrict__ x, const float* __restrict__ mt,
                        const float* __restrict__ td, const float* __restrict__ rd) {
    int tid = threadIdx.x;
    for (int o = tid; o < 1024; o += 256) {
        int e = o & 1, c2 = (o >> 1) & 15, k = (o >> 5) & 3, b = o >> 7;
        float s = 0.f;
        #pragma unroll
        for (int c = 0; c < 16; ++c)
            s += x[b * 16 + c] * mt[(k * 16 + c) * 32 + c2 * 2 + e];
        g_t[b][k][c2][e] = s;
    }
    if (tid == 0) {
        float A = 0.f, Bv = 0.f, K = 0.f;
        for (int c = 0; c < 16; ++c) {
            float rr = rd[2 * c], ri = rd[2 * c + 1];
            float tr = td[2 * c], ti = td[2 * c + 1];
            A += ri; Bv -= rr; K += ti * ri - tr * rr;
        }
        g_scal[0] = A; g_scal[1] = Bv; g_scal[2] = K;
    }
}

// ---------------- k_mimj ----------------
__global__ void k_mimj(const float* __restrict__ mod_i, const float* __restrict__ mod_j,
                       const float* __restrict__ inv) {
    int b = blockIdx.x >> 4, r = blockIdx.x & 15, m = threadIdx.x;
    __shared__ float st[16][8];
    __shared__ float siv[16][2];
    if (m < 128) st[m >> 3][m & 7] = g_t[b][(m & 7) >> 1][m >> 3][m & 1];
    if (m < 32)  siv[m >> 1][m & 1] = inv[m];
    __syncthreads();

    float sir = 0.f, sii = 0.f, sjr = 0.f, sji = 0.f;
    #pragma unroll 4
    for (int c = 0; c < 16; ++c) {
        float t0r = st[c][0], t0i = st[c][1], t1r = st[c][2], t1i = st[c][3];
        float t2r = st[c][4], t2i = st[c][5], t3r = st[c][6], t3i = st[c][7];
        float ivr = siv[c][0], ivi = siv[c][1];
        float2 vi = ((const float2*)mod_i)[(c * 16 + r) * 512 + m];
        float ar = vi.x + t0r, ai = vi.y + t0i;
        float r1 = ai * t1i - ar * t1r;
        float i1 = ar * t1i + ai * t1r;
        sir += i1 * ivi - r1 * ivr;
        sii += r1 * ivi + i1 * ivr;
        float2 vj = ((const float2*)mod_j)[(c * 16 + r) * 512 + m];
        float br2 = vj.x + t2r, bi2 = vj.y + t2i;
        float r2 = bi2 * t3i - br2 * t3r;
        float i2 = br2 * t3i + bi2 * t3r;
        float idn = 1.f / (r2 * r2 + i2 * i2);
        sjr += (ivr * r2 + ivi * i2) * idn;
        sji += (ivr * i2 - ivi * r2) * idn;
    }
    g_mi[b][0][r][m] = sir; g_mi[b][1][r][m] = sii;
    g_mj[b][0][r][m] = sjr; g_mj[b][1][r][m] = sji;
}

// ---------------- k_mod ----------------
__global__ void k_mod() {
    int b = blockIdx.x >> 9, m = blockIdx.x & 511;
    int tid = threadIdx.x;
    __shared__ float smi[2][16];
    if (tid < 32) smi[tid >> 4][tid & 15] = g_mi[b][tid >> 4][tid & 15][m];
    __syncthreads();
    float s1 = 0.f, s2 = 0.f;
    #pragma unroll
    for (int q = 0; q < 4; ++q) {
        int n = tid + q * 128;
        float cr = 0.f, ci = 0.f;
        #pragma unroll
        for (int r = 0; r < 16; ++r) {
            float air = smi[0][r], aii = smi[1][r];
            float bjr = g_mj[b][0][r][n], bji = g_mj[b][1][r][n];
            cr += air * bjr - aii * bji;
            ci += air * bji + aii * bjr;
        }
        g_mod[b][0][m * 512 + n] = cr;
        g_mod[b][1][m * 512 + n] = ci;
        s1 += cr; s2 += cr * cr;
    }
    __shared__ float rs1[128], rs2[128];
    rs1[tid] = s1; rs2[tid] = s2; __syncthreads();
    for (int off = 64; off; off >>= 1) {
        if (tid < off) { rs1[tid] += rs1[tid + off]; rs2[tid] += rs2[tid + off]; }
        __syncthreads();
    }
    if (tid == 0) { g_part[b][m][0] = rs1[0]; g_part[b][m][1] = rs2[0]; }
}

// ---------------- k_stats ----------------
__global__ void k_stats() {
    int b = blockIdx.x, t = threadIdx.x;
    __shared__ float r1[256], r2[256];
    r1[t] = g_part[b][t][0] + g_part[b][t + 256][0];
    r2[t] = g_part[b][t][1] + g_part[b][t + 256][1];
    __syncthreads();
    for (int off = 128; off; off >>= 1) {
        if (t < off) { r1[t] += r1[t + off]; r2[t] += r2[t + off]; }
        __syncthreads();
    }
    if (t == 0) { g_stats[b][0] = r1[0]; g_stats[b][1] = r2[0]; }
}

// ---------------- k_packA0: Wi -> A0 = [Wir^T | Wii^T], fp16 hi/lo ----------------
__global__ void k_packA0(const float* __restrict__ Wi) {
    int mt = blockIdx.x * 32, pt = blockIdx.y * 32;
    __shared__ float sr[32][33], si[32][33];
    int t = threadIdx.x;
    #pragma unroll
    for (int rr = 0; rr < 4; ++rr) {
        int e = t + 256 * rr, ml = e >> 5, pl = e & 31;
        float2 v = ((const float2*)Wi)[(mt + ml) * 512 + pt + pl];
        sr[ml][pl] = v.x; si[ml][pl] = v.y;
    }
    __syncthreads();
    int pl = t >> 3, m4 = (t & 7) * 4;
    uint32_t hr[2], lr[2], hi_[2], li_[2];
    #pragma unroll
    for (int g = 0; g < 2; ++g) {
        split2h(sr[m4 + 2 * g][pl], sr[m4 + 2 * g + 1][pl], hr[g], lr[g]);
        split2h(si[m4 + 2 * g][pl], si[m4 + 2 * g + 1][pl], hi_[g], li_[g]);
    }
    size_t row = (size_t)(pt + pl) * 1024;
    int col = mt + m4;
    *(uint2*)(g_A0h + row + col)       = make_uint2(hr[0], hr[1]);
    *(uint2*)(g_A0l + row + col)       = make_uint2(lr[0], lr[1]);
    *(uint2*)(g_A0h + row + 512 + col) = make_uint2(hi_[0], hi_[1]);
    *(uint2*)(g_A0l + row + 512 + col) = make_uint2(li_[0], li_[1]);
}

// ---------------- k_packB1: Wj -> B1 (hi only), rows 2n' = [Wjr | -Wji], 2n'+1 = [Wji | Wjr] ----
__global__ void k_packB1(const float* __restrict__ Wj) {
    int nt = blockIdx.x * 32, pt = blockIdx.y * 32;
    __shared__ float sr[32][33], si[32][33];
    int t = threadIdx.x;
    #pragma unroll
    for (int rr = 0; rr < 4; ++rr) {
        int e = t + 256 * rr, nl = e >> 5, pl = e & 31;
        float2 v = ((const float2*)Wj)[(nt + nl) * 512 + pt + pl];
        sr[nl][pl] = v.x; si[nl][pl] = v.y;
    }
    __syncthreads();
    int pl = t >> 3, m4 = (t & 7) * 4;
    uint32_t hr[2], hi_[2];
    #pragma unroll
    for (int g = 0; g < 2; ++g) {
        hr[g]  = h2_rn(sr[m4 + 2 * g][pl], sr[m4 + 2 * g + 1][pl]);
        hi_[g] = h2_rn(si[m4 + 2 * g][pl], si[m4 + 2 * g + 1][pl]);
    }
    int np = pt + pl;
    size_t row_r = (size_t)(2 * np) * 1024;
    size_t row_i = (size_t)(2 * np + 1) * 1024;
    int col = nt + m4;
    *(uint2*)(g_B1h + row_r + col)       = make_uint2(hr[0], hr[1]);
    *(uint2*)(g_B1h + row_r + 512 + col) = make_uint2(hi_[0] ^ 0x80008000u, hi_[1] ^ 0x80008000u);
    *(uint2*)(g_B1h + row_i + col)       = make_uint2(hi_[0], hi_[1]);
    *(uint2*)(g_B1h + row_i + 512 + col) = make_uint2(hr[0], hr[1]);
}

// ---------------- k_packB0: wd0 -> B0 block matrix (hi only) per batch ----------------
__global__ void k_packB0(const float* __restrict__ wb) {
    int mt = blockIdx.x * 32, nt = blockIdx.y * 32, b = blockIdx.z;
    float s1 = g_stats[b][0], s2 = g_stats[b][1];
    float mean = s1 * (1.f / 262144.f);
    float var = (s2 - s1 * mean) * (1.f / 262143.f);
    float istd = rsqrtf(var);
    __shared__ float wr[32][33], wi[32][33];
    int t = threadIdx.x;
    #pragma unroll
    for (int rr = 0; rr < 4; ++rr) {
        int e = t + 256 * rr, ml = e >> 5, nl = e & 31;
        int idx = (mt + ml) * 512 + nt + nl;
        float2 w = ((const float2*)wb)[idx];
        wr[ml][nl] = w.x * (1.f + (g_mod[b][0][idx] - mean) * istd);
        wi[ml][nl] = w.y * (1.f + g_mod[b][1][idx]);
    }
    __syncthreads();
    int nl = t >> 3, m4 = (t & 7) * 4;
    uint32_t hr[2], hi_[2];
    #pragma unroll
    for (int g = 0; g < 2; ++g) {
        hr[g]  = h2_rn(wr[m4 + 2 * g][nl], wr[m4 + 2 * g + 1][nl]);
        hi_[g] = h2_rn(wi[m4 + 2 * g][nl], wi[m4 + 2 * g + 1][nl]);
    }
    size_t row_r = (size_t)(nt + nl) * 1024;
    size_t row_i = (size_t)(512 + nt + nl) * 1024;
    int col = mt + m4;
    half* Bh = g_B0h[b];
    *(uint2*)(Bh + row_r + col)       = make_uint2(hr[0], hr[1]);
    *(uint2*)(Bh + row_r + 512 + col) = make_uint2(hi_[0] ^ 0x80008000u, hi_[1] ^ 0x80008000u);
    *(uint2*)(Bh + row_i + col)       = make_uint2(hi_[0], hi_[1]);
    *(uint2*)(Bh + row_i + 512 + col) = make_uint2(hr[0], hr[1]);
}

// ---------------- mma.sync GEMM: fp16 2-pass, K-chunk 64, 2-stage, 2 CTAs/SM ----------------
// buffer (48KB): Ah @0, Al @16K, Bh @32K. rows: 128 x 128B, SWZ.
__device__ __forceinline__ void prefetch_chunk(
    const half* __restrict__ Ah, const half* __restrict__ Al, const half* __restrict__ Bh,
    int arow, int brow, int kb, uint32_t sdst, int tid) {
    const half* srcs[3] = { Ah, Al, Bh };
    const int rows0[3] = { arow, arow, brow };
    #pragma unroll
    for (int arr = 0; arr < 3; ++arr) {
        #pragma unroll
        for (int i = 0; i < 4; ++i) {
            int u = tid + 256 * i, row = u >> 3, seg = u & 7;
            const half* g = srcs[arr] + (size_t)(rows0[arr] + row) * 1024 + kb + seg * 8;
            uint32_t s = sdst + arr * 16384 + SWZ(row * 128 + seg * 16);
            CP_ASYNC16(s, g);
        }
    }
    CP_COMMIT();
}

template<int STAGE>
__global__ void __launch_bounds__(256, 2) k_mma(float* __restrict__ gout) {
    extern __shared__ __align__(1024) char smem[];
    const int tid = threadIdx.x, wid = tid >> 5, lane = tid & 31;
    const int wm = wid >> 1, wn = wid & 1;
    const int b = blockIdx.z, My = blockIdx.y, Nx = blockIdx.x;
    const half *Ah, *Al, *Bh;
    if (STAGE == 0) { Ah = g_A0h;    Al = g_A0l;    Bh = g_B0h[b]; }
    else            { Ah = g_A1h[b]; Al = g_A1l[b]; Bh = g_B1h; }
    const int arow = My * 128, brow = Nx * 128;
    const uint32_t sb = smem_u32(smem);

    float c[2][8][4];
    #pragma unroll
    for (int mt = 0; mt < 2; ++mt)
        #pragma unroll
        for (int nt = 0; nt < 8; ++nt)
            #pragma unroll
            for (int q = 0; q < 4; ++q) c[mt][nt][q] = 0.f;

    prefetch_chunk(Ah, Al, Bh, arow, brow, 0, sb, tid);

    for (int ch = 0; ch < 16; ++ch) {
        const uint32_t sbuf = sb + (ch & 1) * 49152;
        if (ch + 1 < 16) {
            prefetch_chunk(Ah, Al, Bh, arow, brow, (ch + 1) * 64,
                           sb + ((ch + 1) & 1) * 49152, tid);
            CP_WAIT(1);
        } else {
            CP_WAIT(0);
        }
        __syncthreads();

        const uint32_t sA = sbuf, sAl = sbuf + 16384, sB = sbuf + 32768;
        #pragma unroll
        for (int ks = 0; ks < 4; ++ks) {
            uint32_t ah[2][4], al[2][4], bh[8][2];
            #pragma unroll
            for (int mt = 0; mt < 2; ++mt) {
                int row = wm * 32 + mt * 16 + (lane & 15);
                uint32_t off = SWZ(row * 128 + ks * 32 + (lane >> 4) * 16);
                LDSM_X4(ah[mt][0], ah[mt][1], ah[mt][2], ah[mt][3], sA + off);
                LDSM_X4(al[mt][0], al[mt][1], al[mt][2], al[mt][3], sAl + off);
            }
            #pragma unroll
            for (int ntp = 0; ntp < 4; ++ntp) {
                int row = wn * 64 + ntp * 16 + (lane >> 4) * 8 + (lane & 7);
                uint32_t off = SWZ(row * 128 + ks * 32 + ((lane >> 3) & 1) * 16);
                LDSM_X4(bh[2 * ntp][0], bh[2 * ntp][1], bh[2 * ntp + 1][0], bh[2 * ntp + 1][1], sB + off);
            }
            #pragma unroll
            for (int mt = 0; mt < 2; ++mt)
                #pragma unroll
                for (int nt = 0; nt < 8; ++nt) {
                    MMA16816(c[mt][nt], ah[mt], bh[nt]);
                    MMA16816(c[mt][nt], al[mt], bh[nt]);
                }
        }
        __syncthreads();
    }

    // ---------------- epilogue ----------------
    const int r0 = My * 128 + wm * 32 + (lane >> 2);
    if (STAGE == 0) {
        half* dh = g_A1h[b]; half* dl = g_A1l[b];
        #pragma unroll
        for (int mt = 0; mt < 2; ++mt)
            #pragma unroll
            for (int nt = 0; nt < 8; ++nt) {
                int row = r0 + mt * 16;
                int col = Nx * 128 + wn * 64 + nt * 8 + 2 * (lane & 3);
                uint32_t h, l;
                split2h(c[mt][nt][0], c[mt][nt][1], h, l);
                *(uint32_t*)(dh + (size_t)row * 1024 + col) = h;
                *(uint32_t*)(dl + (size_t)row * 1024 + col) = l;
                split2h(c[mt][nt][2], c[mt][nt][3], h, l);
                *(uint32_t*)(dh + (size_t)(row + 8) * 1024 + col) = h;
                *(uint32_t*)(dl + (size_t)(row + 8) * 1024 + col) = l;
            }
    } else {
        const float A_ = g_scal[0], B_ = g_scal[1], K_ = g_scal[2];
        float* O = gout + b * PL;
        #pragma unroll
        for (int mt = 0; mt < 2; ++mt)
            #pragma unroll
            for (int nt = 0; nt < 8; ++nt) {
                int row = r0 + mt * 16;
                int np = Nx * 64 + wn * 32 + nt * 4 + (lane & 3);
                O[(size_t)row * 512 + np] =
                    fmaf(c[mt][nt][1], A_, fmaf(c[mt][nt][0], B_, K_));
                O[(size_t)(row + 8) * 512 + np] =
                    fmaf(c[mt][nt][3], A_, fmaf(c[mt][nt][2], B_, K_));
            }
    }
}

// ---------------- launch ----------------
extern "C" void kernel_launch(void* const* d_in, const int* in_sizes, int n_in,
                              void* d_out, int out_size) {
    (void)in_sizes; (void)n_in; (void)out_size;
    const float* x   = (const float*)d_in[0];
    const float* Wi  = (const float*)d_in[1];
    const float* Wj  = (const float*)d_in[2];
    const float* Wb  = (const float*)d_in[3];
    const float* td  = (const float*)d_in[6];
    const float* rd  = (const float*)d_in[7];
    const float* mi  = (const float*)d_in[8];
    const float* mj  = (const float*)d_in[9];
    const float* inv = (const float*)d_in[10];
    const float* mt  = (const float*)d_in[11];
    float* out = (float*)d_out;

    const int SMEM_SZ = 2 * 49152;   // 96 KB -> 2 CTAs/SM
    cudaFuncSetAttribute(k_mma<0>, cudaFuncAttributeMaxDynamicSharedMemorySize, SMEM_SZ);
    cudaFuncSetAttribute(k_mma<1>, cudaFuncAttributeMaxDynamicSharedMemorySize, SMEM_SZ);

    k_setup<<<1, 256>>>(x, mt, td, rd);
    k_mimj<<<128, 512>>>(mi, mj, inv);
    k_mod<<<4096, 128>>>();
    k_stats<<<8, 256>>>();
    k_packA0<<<dim3(16, 16), 256>>>(Wi);
    k_packB1<<<dim3(16, 16), 256>>>(Wj);
    k_packB0<<<dim3(16, 16, 8), 256>>>(Wb);
    dim3 grid(8, 4, 8);
    k_mma<0><<<grid, 256, SMEM_SZ>>>(nullptr);
    k_mma<1><<<grid, 256, SMEM_SZ>>>(out);
}

// round 12
// speedup vs baseline: 1.7649x; 1.2061x over previous
#include <cuda_runtime.h>
#include <cuda_fp16.h>
#include <cstdint>

#define PL (512*512)
typedef unsigned long long u64;

// ---------------- scratch ----------------
__device__ float g_t[8][4][16][2];
__device__ float g_scal[3];
__device__ float g_part[8][512][2];
__device__ float g_stats[8][2];
__device__ float g_mi[8][2][16][512];
__device__ float g_mj[8][2][16][512];
__device__ float g_mod[8][2][PL];
__device__ half g_A0h[512 * 1024], g_A0l[512 * 1024];   // Wi^T pack: [m'][k2 = m | 512+m]
__device__ half g_B0h[8][1024 * 1024];                  // wd0 block matrix (hi only)
__device__ half g_A1h[8][512 * 1024];                   // stage-0 out (hi only): [m'][k2' = n | 512+n]
__device__ half g_B1h[1024 * 1024];                     // Wj block matrix, rows 2n'/2n'+1 (hi only)

#define SWZ(x) ((x) ^ (((x) >> 3) & 0x70))

__device__ __forceinline__ uint32_t smem_u32(const void* p) {
    uint32_t a;
    asm("{ .reg .u64 t; cvta.to.shared.u64 t, %1; cvt.u32.u64 %0, t; }" : "=r"(a) : "l"(p));
    return a;
}
// fp16 hi/lo split of a float pair
__device__ __forceinline__ void split2h(float v0, float v1, uint32_t& hi, uint32_t& lo) {
    __half2 h = __floats2half2_rn(v0, v1);
    hi = *(uint32_t*)&h;
    float r0 = v0 - __half2float(__low2half(h));
    float r1 = v1 - __half2float(__high2half(h));
    __half2 l = __floats2half2_rn(r0, r1);
    lo = *(uint32_t*)&l;
}
__device__ __forceinline__ uint32_t h2_rn(float v0, float v1) {
    __half2 h = __floats2half2_rn(v0, v1);
    return *(uint32_t*)&h;
}
#define LDSM_X4(r0, r1, r2, r3, a) \
    asm volatile("ldmatrix.sync.aligned.m8n8.x4.shared.b16 {%0,%1,%2,%3}, [%4];" \
        : "=r"(r0), "=r"(r1), "=r"(r2), "=r"(r3) : "r"(a))
#define MMA16816(c, a, b) \
    asm volatile("mma.sync.aligned.m16n8k16.row.col.f32.f16.f16.f32 " \
        "{%0,%1,%2,%3}, {%4,%5,%6,%7}, {%8,%9}, {%0,%1,%2,%3};" \
        : "+f"((c)[0]), "+f"((c)[1]), "+f"((c)[2]), "+f"((c)[3]) \
        : "r"((a)[0]), "r"((a)[1]), "r"((a)[2]), "r"((a)[3]), "r"((b)[0]), "r"((b)[1]))
#define CP_ASYNC16(s, g) \
    asm volatile("cp.async.cg.shared.global [%0], [%1], 16;" :: "r"(s), "l"(g) : "memory")
#define CP_COMMIT()  asm volatile("cp.async.commit_group;" ::: "memory")
#define CP_WAIT(n)   asm volatile("cp.async.wait_group %0;" :: "n"(n) : "memory")

// ---------------- k_setup ----------------
__global__ void k_setup(const float* __restrict__ x, const float* __restrict__ mt,
                        const float* __restrict__ td, const float* __restrict__ rd) {
    int tid = threadIdx.x;
    for (int o = tid; o < 1024; o += 256) {
        int e = o & 1, c2 = (o >> 1) & 15, k = (o >> 5) & 3, b = o >> 7;
        float s = 0.f;
        #pragma unroll
        for (int c = 0; c < 16; ++c)
            s += x[b * 16 + c] * mt[(k * 16 + c) * 32 + c2 * 2 + e];
        g_t[b][k][c2][e] = s;
    }
    if (tid == 0) {
        float A = 0.f, Bv = 0.f, K = 0.f;
        for (int c = 0; c < 16; ++c) {
            float rr = rd[2 * c], ri = rd[2 * c + 1];
            float tr = td[2 * c], ti = td[2 * c + 1];
            A += ri; Bv -= rr; K += ti * ri - tr * rr;
        }
        g_scal[0] = A; g_scal[1] = Bv; g_scal[2] = K;
    }
}

// ---------------- k_mimj ----------------
__global__ void k_mimj(const float* __restrict__ mod_i, const float* __restrict__ mod_j,
                       const float* __restrict__ inv) {
    int b = blockIdx.x >> 4, r = blockIdx.x & 15, m = threadIdx.x;
    __shared__ float st[16][8];
    __shared__ float siv[16][2];
    if (m < 128) st[m >> 3][m & 7] = g_t[b][(m & 7) >> 1][m >> 3][m & 1];
    if (m < 32)  siv[m >> 1][m & 1] = inv[m];
    __syncthreads();

    float sir = 0.f, sii = 0.f, sjr = 0.f, sji = 0.f;
    #pragma unroll 4
    for (int c = 0; c < 16; ++c) {
        float t0r = st[c][0], t0i = st[c][1], t1r = st[c][2], t1i = st[c][3];
        float t2r = st[c][4], t2i = st[c][5], t3r = st[c][6], t3i = st[c][7];
        float ivr = siv[c][0], ivi = siv[c][1];
        float2 vi = ((const float2*)mod_i)[(c * 16 + r) * 512 + m];
        float ar = vi.x + t0r, ai = vi.y + t0i;
        float r1 = ai * t1i - ar * t1r;
        float i1 = ar * t1i + ai * t1r;
        sir += i1 * ivi - r1 * ivr;
        sii += r1 * ivi + i1 * ivr;
        float2 vj = ((const float2*)mod_j)[(c * 16 + r) * 512 + m];
        float br2 = vj.x + t2r, bi2 = vj.y + t2i;
        float r2 = bi2 * t3i - br2 * t3r;
        float i2 = br2 * t3i + bi2 * t3r;
        float idn = 1.f / (r2 * r2 + i2 * i2);
        sjr += (ivr * r2 + ivi * i2) * idn;
        sji += (ivr * i2 - ivi * r2) * idn;
    }
    g_mi[b][0][r][m] = sir; g_mi[b][1][r][m] = sii;
    g_mj[b][0][r][m] = sjr; g_mj[b][1][r][m] = sji;
}

// ---------------- k_mod ----------------
__global__ void k_mod() {
    int b = blockIdx.x >> 9, m = blockIdx.x & 511;
    int tid = threadIdx.x;
    __shared__ float smi[2][16];
    if (tid < 32) smi[tid >> 4][tid & 15] = g_mi[b][tid >> 4][tid & 15][m];
    __syncthreads();
    float s1 = 0.f, s2 = 0.f;
    #pragma unroll
    for (int q = 0; q < 4; ++q) {
        int n = tid + q * 128;
        float cr = 0.f, ci = 0.f;
        #pragma unroll
        for (int r = 0; r < 16; ++r) {
            float air = smi[0][r], aii = smi[1][r];
            float bjr = g_mj[b][0][r][n], bji = g_mj[b][1][r][n];
            cr += air * bjr - aii * bji;
            ci += air * bji + aii * bjr;
        }
        g_mod[b][0][m * 512 + n] = cr;
        g_mod[b][1][m * 512 + n] = ci;
        s1 += cr; s2 += cr * cr;
    }
    __shared__ float rs1[128], rs2[128];
    rs1[tid] = s1; rs2[tid] = s2; __syncthreads();
    for (int off = 64; off; off >>= 1) {
        if (tid < off) { rs1[tid] += rs1[tid + off]; rs2[tid] += rs2[tid + off]; }
        __syncthreads();
    }
    if (tid == 0) { g_part[b][m][0] = rs1[0]; g_part[b][m][1] = rs2[0]; }
}

// ---------------- k_stats ----------------
__global__ void k_stats() {
    int b = blockIdx.x, t = threadIdx.x;
    __shared__ float r1[256], r2[256];
    r1[t] = g_part[b][t][0] + g_part[b][t + 256][0];
    r2[t] = g_part[b][t][1] + g_part[b][t + 256][1];
    __syncthreads();
    for (int off = 128; off; off >>= 1) {
        if (t < off) { r1[t] += r1[t + off]; r2[t] += r2[t + off]; }
        __syncthreads();
    }
    if (t == 0) { g_stats[b][0] = r1[0]; g_stats[b][1] = r2[0]; }
}

// ---------------- k_packA0: Wi -> A0 = [Wir^T | Wii^T], fp16 hi/lo ----------------
__global__ void k_packA0(const float* __restrict__ Wi) {
    int mt = blockIdx.x * 32, pt = blockIdx.y * 32;
    __shared__ float sr[32][33], si[32][33];
    int t = threadIdx.x;
    #pragma unroll
    for (int rr = 0; rr < 4; ++rr) {
        int e = t + 256 * rr, ml = e >> 5, pl = e & 31;
        float2 v = ((const float2*)Wi)[(mt + ml) * 512 + pt + pl];
        sr[ml][pl] = v.x; si[ml][pl] = v.y;
    }
    __syncthreads();
    int pl = t >> 3, m4 = (t & 7) * 4;
    uint32_t hr[2], lr[2], hi_[2], li_[2];
    #pragma unroll
    for (int g = 0; g < 2; ++g) {
        split2h(sr[m4 + 2 * g][pl], sr[m4 + 2 * g + 1][pl], hr[g], lr[g]);
        split2h(si[m4 + 2 * g][pl], si[m4 + 2 * g + 1][pl], hi_[g], li_[g]);
    }
    size_t row = (size_t)(pt + pl) * 1024;
    int col = mt + m4;
    *(uint2*)(g_A0h + row + col)       = make_uint2(hr[0], hr[1]);
    *(uint2*)(g_A0l + row + col)       = make_uint2(lr[0], lr[1]);
    *(uint2*)(g_A0h + row + 512 + col) = make_uint2(hi_[0], hi_[1]);
    *(uint2*)(g_A0l + row + 512 + col) = make_uint2(li_[0], li_[1]);
}

// ---------------- k_packB1: Wj -> B1 (hi only), rows 2n' = [Wjr | -Wji], 2n'+1 = [Wji | Wjr] ----
__global__ void k_packB1(const float* __restrict__ Wj) {
    int nt = blockIdx.x * 32, pt = blockIdx.y * 32;
    __shared__ float sr[32][33], si[32][33];
    int t = threadIdx.x;
    #pragma unroll
    for (int rr = 0; rr < 4; ++rr) {
        int e = t + 256 * rr, nl = e >> 5, pl = e & 31;
        float2 v = ((const float2*)Wj)[(nt + nl) * 512 + pt + pl];
        sr[nl][pl] = v.x; si[nl][pl] = v.y;
    }
    __syncthreads();
    int pl = t >> 3, m4 = (t & 7) * 4;
    uint32_t hr[2], hi_[2];
    #pragma unroll
    for (int g = 0; g < 2; ++g) {
        hr[g]  = h2_rn(sr[m4 + 2 * g][pl], sr[m4 + 2 * g + 1][pl]);
        hi_[g] = h2_rn(si[m4 + 2 * g][pl], si[m4 + 2 * g + 1][pl]);
    }
    int np = pt + pl;
    size_t row_r = (size_t)(2 * np) * 1024;
    size_t row_i = (size_t)(2 * np + 1) * 1024;
    int col = nt + m4;
    *(uint2*)(g_B1h + row_r + col)       = make_uint2(hr[0], hr[1]);
    *(uint2*)(g_B1h + row_r + 512 + col) = make_uint2(hi_[0] ^ 0x80008000u, hi_[1] ^ 0x80008000u);
    *(uint2*)(g_B1h + row_i + col)       = make_uint2(hi_[0], hi_[1]);
    *(uint2*)(g_B1h + row_i + 512 + col) = make_uint2(hr[0], hr[1]);
}

// ---------------- k_packB0: wd0 -> B0 block matrix (hi only) per batch ----------------
__global__ void k_packB0(const float* __restrict__ wb) {
    int mt = blockIdx.x * 32, nt = blockIdx.y * 32, b = blockIdx.z;
    float s1 = g_stats[b][0], s2 = g_stats[b][1];
    float mean = s1 * (1.f / 262144.f);
    float var = (s2 - s1 * mean) * (1.f / 262143.f);
    float istd = rsqrtf(var);
    __shared__ float wr[32][33], wi[32][33];
    int t = threadIdx.x;
    #pragma unroll
    for (int rr = 0; rr < 4; ++rr) {
        int e = t + 256 * rr, ml = e >> 5, nl = e & 31;
        int idx = (mt + ml) * 512 + nt + nl;
        float2 w = ((const float2*)wb)[idx];
        wr[ml][nl] = w.x * (1.f + (g_mod[b][0][idx] - mean) * istd);
        wi[ml][nl] = w.y * (1.f + g_mod[b][1][idx]);
    }
    __syncthreads();
    int nl = t >> 3, m4 = (t & 7) * 4;
    uint32_t hr[2], hi_[2];
    #pragma unroll
    for (int g = 0; g < 2; ++g) {
        hr[g]  = h2_rn(wr[m4 + 2 * g][nl], wr[m4 + 2 * g + 1][nl]);
        hi_[g] = h2_rn(wi[m4 + 2 * g][nl], wi[m4 + 2 * g + 1][nl]);
    }
    size_t row_r = (size_t)(nt + nl) * 1024;
    size_t row_i = (size_t)(512 + nt + nl) * 1024;
    int col = mt + m4;
    half* Bh = g_B0h[b];
    *(uint2*)(Bh + row_r + col)       = make_uint2(hr[0], hr[1]);
    *(uint2*)(Bh + row_r + 512 + col) = make_uint2(hi_[0] ^ 0x80008000u, hi_[1] ^ 0x80008000u);
    *(uint2*)(Bh + row_i + col)       = make_uint2(hi_[0], hi_[1]);
    *(uint2*)(Bh + row_i + 512 + col) = make_uint2(hr[0], hr[1]);
}

// ---------------- mma.sync GEMM ----------------
// STAGE 0: 2-pass (Ah,Al)·Bh, buffer 48KB {Ah@0, Al@16K, Bh@32K}
// STAGE 1: 1-pass  Ah·Bh,     buffer 32KB {Ah@0, Bh@16K}
template<int NPASS>
__device__ __forceinline__ void prefetch_chunk(
    const half* __restrict__ Ah, const half* __restrict__ Al, const half* __restrict__ Bh,
    int arow, int brow, int kb, uint32_t sdst, int tid) {
    const half* srcs[3];
    int rows0[3];
    srcs[0] = Ah; rows0[0] = arow;
    if (NPASS == 2) { srcs[1] = Al; rows0[1] = arow; srcs[2] = Bh; rows0[2] = brow; }
    else            { srcs[1] = Bh; rows0[1] = brow; }
    #pragma unroll
    for (int arr = 0; arr < NPASS + 1; ++arr) {
        #pragma unroll
        for (int i = 0; i < 4; ++i) {
            int u = tid + 256 * i, row = u >> 3, seg = u & 7;
            const half* g = srcs[arr] + (size_t)(rows0[arr] + row) * 1024 + kb + seg * 8;
            uint32_t s = sdst + arr * 16384 + SWZ(row * 128 + seg * 16);
            CP_ASYNC16(s, g);
        }
    }
    CP_COMMIT();
}

template<int STAGE>
__global__ void __launch_bounds__(256, 2) k_mma(float* __restrict__ gout) {
    constexpr int NPASS = (STAGE == 0) ? 2 : 1;
    constexpr int BUFSZ = (NPASS + 1) * 16384;
    extern __shared__ __align__(1024) char smem[];
    const int tid = threadIdx.x, wid = tid >> 5, lane = tid & 31;
    const int wm = wid >> 1, wn = wid & 1;
    const int b = blockIdx.z, My = blockIdx.y, Nx = blockIdx.x;
    const half *Ah, *Al = nullptr, *Bh;
    if (STAGE == 0) { Ah = g_A0h; Al = g_A0l; Bh = g_B0h[b]; }
    else            { Ah = g_A1h[b];          Bh = g_B1h; }
    const int arow = My * 128, brow = Nx * 128;
    const uint32_t sb = smem_u32(smem);

    float c[2][8][4];
    #pragma unroll
    for (int mt = 0; mt < 2; ++mt)
        #pragma unroll
        for (int nt = 0; nt < 8; ++nt)
            #pragma unroll
            for (int q = 0; q < 4; ++q) c[mt][nt][q] = 0.f;

    prefetch_chunk<NPASS>(Ah, Al, Bh, arow, brow, 0, sb, tid);

    for (int ch = 0; ch < 16; ++ch) {
        const uint32_t sbuf = sb + (ch & 1) * BUFSZ;
        if (ch + 1 < 16) {
            prefetch_chunk<NPASS>(Ah, Al, Bh, arow, brow, (ch + 1) * 64,
                                  sb + ((ch + 1) & 1) * BUFSZ, tid);
            CP_WAIT(1);
        } else {
            CP_WAIT(0);
        }
        __syncthreads();

        const uint32_t sA = sbuf;
        const uint32_t sAl = sbuf + 16384;              // valid when NPASS==2
        const uint32_t sB = sbuf + NPASS * 16384;
        #pragma unroll
        for (int ks = 0; ks < 4; ++ks) {
            uint32_t ah[2][4], al[2][4], bh[8][2];
            #pragma unroll
            for (int mt = 0; mt < 2; ++mt) {
                int row = wm * 32 + mt * 16 + (lane & 15);
                uint32_t off = SWZ(row * 128 + ks * 32 + (lane >> 4) * 16);
                LDSM_X4(ah[mt][0], ah[mt][1], ah[mt][2], ah[mt][3], sA + off);
                if (NPASS == 2)
                    LDSM_X4(al[mt][0], al[mt][1], al[mt][2], al[mt][3], sAl + off);
            }
            #pragma unroll
            for (int ntp = 0; ntp < 4; ++ntp) {
                int row = wn * 64 + ntp * 16 + (lane >> 4) * 8 + (lane & 7);
                uint32_t off = SWZ(row * 128 + ks * 32 + ((lane >> 3) & 1) * 16);
                LDSM_X4(bh[2 * ntp][0], bh[2 * ntp][1], bh[2 * ntp + 1][0], bh[2 * ntp + 1][1], sB + off);
            }
            #pragma unroll
            for (int mt = 0; mt < 2; ++mt)
                #pragma unroll
                for (int nt = 0; nt < 8; ++nt) {
                    MMA16816(c[mt][nt], ah[mt], bh[nt]);
                    if (NPASS == 2)
                        MMA16816(c[mt][nt], al[mt], bh[nt]);
                }
        }
        __syncthreads();
    }

    // ---------------- epilogue ----------------
    const int r0 = My * 128 + wm * 32 + (lane >> 2);
    if (STAGE == 0) {
        half* dh = g_A1h[b];
        #pragma unroll
        for (int mt = 0; mt < 2; ++mt)
            #pragma unroll
            for (int nt = 0; nt < 8; ++nt) {
                int row = r0 + mt * 16;
                int col = Nx * 128 + wn * 64 + nt * 8 + 2 * (lane & 3);
                *(uint32_t*)(dh + (size_t)row * 1024 + col)       = h2_rn(c[mt][nt][0], c[mt][nt][1]);
                *(uint32_t*)(dh + (size_t)(row + 8) * 1024 + col) = h2_rn(c[mt][nt][2], c[mt][nt][3]);
            }
    } else {
        const float A_ = g_scal[0], B_ = g_scal[1], K_ = g_scal[2];
        float* O = gout + b * PL;
        #pragma unroll
        for (int mt = 0; mt < 2; ++mt)
            #pragma unroll
            for (int nt = 0; nt < 8; ++nt) {
                int row = r0 + mt * 16;
                int np = Nx * 64 + wn * 32 + nt * 4 + (lane & 3);
                O[(size_t)row * 512 + np] =
                    fmaf(c[mt][nt][1], A_, fmaf(c[mt][nt][0], B_, K_));
                O[(size_t)(row + 8) * 512 + np] =
                    fmaf(c[mt][nt][3], A_, fmaf(c[mt][nt][2], B_, K_));
            }
    }
}

// ---------------- launch ----------------
extern "C" void kernel_launch(void* const* d_in, const int* in_sizes, int n_in,
                              void* d_out, int out_size) {
    (void)in_sizes; (void)n_in; (void)out_size;
    const float* x   = (const float*)d_in[0];
    const float* Wi  = (const float*)d_in[1];
    const float* Wj  = (const float*)d_in[2];
    const float* Wb  = (const float*)d_in[3];
    const float* td  = (const float*)d_in[6];
    const float* rd  = (const float*)d_in[7];
    const float* mi  = (const float*)d_in[8];
    const float* mj  = (const float*)d_in[9];
    const float* inv = (const float*)d_in[10];
    const float* mt  = (const float*)d_in[11];
    float* out = (float*)d_out;

    const int SMEM0 = 2 * 49152;   // 96 KB, 2 CTAs/SM
    const int SMEM1 = 2 * 32768;   // 64 KB, 2 CTAs/SM
    cudaFuncSetAttribute(k_mma<0>, cudaFuncAttributeMaxDynamicSharedMemorySize, SMEM0);
    cudaFuncSetAttribute(k_mma<1>, cudaFuncAttributeMaxDynamicSharedMemorySize, SMEM1);

    k_setup<<<1, 256>>>(x, mt, td, rd);
    k_mimj<<<128, 512>>>(mi, mj, inv);
    k_mod<<<4096, 128>>>();
    k_stats<<<8, 256>>>();
    k_packA0<<<dim3(16, 16), 256>>>(Wi);
    k_packB1<<<dim3(16, 16), 256>>>(Wj);
    k_packB0<<<dim3(16, 16, 8), 256>>>(Wb);
    dim3 grid(8, 4, 8);
    k_mma<0><<<grid, 256, SMEM0>>>(nullptr);
    k_mma<1><<<grid, 256, SMEM1>>>(out);
}

// round 14
// speedup vs baseline: 1.8620x; 1.0550x over previous
#include <cuda_runtime.h>
#include <cuda_fp16.h>
#include <cstdint>

#define PL (512*512)
typedef unsigned long long u64;

// ---------------- scratch ----------------
__device__ float g_t[8][4][16][2];
__device__ float g_scal[3];
__device__ float g_part[8][32][2];
__device__ float g_stats[8][2];
__device__ float g_mi[8][2][16][512];
__device__ float g_mj[8][2][16][512];
__device__ float g_mod[8][2][PL];
__device__ half g_A0h[512 * 1024];       // Wi^T pack (hi only): [m'][k2 = m | 512+m]
__device__ half g_B0h[8][1024 * 1024];   // wd0 block matrix (hi only)
__device__ half g_A1h[8][512 * 1024];    // stage-0 out (hi only): [m'][k2' = n | 512+n]
__device__ half g_B1h[1024 * 1024];      // Wj block matrix, rows 2n'/2n'+1 (hi only)

#define SWZ(x) ((x) ^ (((x) >> 3) & 0x70))

__device__ __forceinline__ uint32_t smem_u32(const void* p) {
    uint32_t a;
    asm("{ .reg .u64 t; cvta.to.shared.u64 t, %1; cvt.u32.u64 %0, t; }" : "=r"(a) : "l"(p));
    return a;
}
__device__ __forceinline__ uint32_t h2_rn(float v0, float v1) {
    __half2 h = __floats2half2_rn(v0, v1);
    return *(uint32_t*)&h;
}
#define LDSM_X4(r0, r1, r2, r3, a) \
    asm volatile("ldmatrix.sync.aligned.m8n8.x4.shared.b16 {%0,%1,%2,%3}, [%4];" \
        : "=r"(r0), "=r"(r1), "=r"(r2), "=r"(r3) : "r"(a))
#define MMA16816(c, a, b) \
    asm volatile("mma.sync.aligned.m16n8k16.row.col.f32.f16.f16.f32 " \
        "{%0,%1,%2,%3}, {%4,%5,%6,%7}, {%8,%9}, {%0,%1,%2,%3};" \
        : "+f"((c)[0]), "+f"((c)[1]), "+f"((c)[2]), "+f"((c)[3]) \
        : "r"((a)[0]), "r"((a)[1]), "r"((a)[2]), "r"((a)[3]), "r"((b)[0]), "r"((b)[1]))
#define CP_ASYNC16(s, g) \
    asm volatile("cp.async.cg.shared.global [%0], [%1], 16;" :: "r"(s), "l"(g) : "memory")
#define CP_COMMIT()  asm volatile("cp.async.commit_group;" ::: "memory")
#define CP_WAIT(n)   asm volatile("cp.async.wait_group %0;" :: "n"(n) : "memory")

// ---------------- k_setup ----------------
__global__ void k_setup(const float* __restrict__ x, const float* __restrict__ mt,
                        const float* __restrict__ td, const float* __restrict__ rd) {
    int tid = threadIdx.x;
    for (int o = tid; o < 1024; o += 256) {
        int e = o & 1, c2 = (o >> 1) & 15, k = (o >> 5) & 3, b = o >> 7;
        float s = 0.f;
        #pragma unroll
        for (int c = 0; c < 16; ++c)
            s += x[b * 16 + c] * mt[(k * 16 + c) * 32 + c2 * 2 + e];
        g_t[b][k][c2][e] = s;
    }
    if (tid == 0) {
        float A = 0.f, Bv = 0.f, K = 0.f;
        for (int c = 0; c < 16; ++c) {
            float rr = rd[2 * c], ri = rd[2 * c + 1];
            float tr = td[2 * c], ti = td[2 * c + 1];
            A += ri; Bv -= rr; K += ti * ri - tr * rr;
        }
        g_scal[0] = A; g_scal[1] = Bv; g_scal[2] = K;
    }
}

// ---------------- k_mimj ----------------
__global__ void k_mimj(const float* __restrict__ mod_i, const float* __restrict__ mod_j,
                       const float* __restrict__ inv) {
    int b = blockIdx.x >> 4, r = blockIdx.x & 15, m = threadIdx.x;
    __shared__ float st[16][8];
    __shared__ float siv[16][2];
    if (m < 128) st[m >> 3][m & 7] = g_t[b][(m & 7) >> 1][m >> 3][m & 1];
    if (m < 32)  siv[m >> 1][m & 1] = inv[m];
    __syncthreads();

    float sir = 0.f, sii = 0.f, sjr = 0.f, sji = 0.f;
    #pragma unroll 4
    for (int c = 0; c < 16; ++c) {
        float t0r = st[c][0], t0i = st[c][1], t1r = st[c][2], t1i = st[c][3];
        float t2r = st[c][4], t2i = st[c][5], t3r = st[c][6], t3i = st[c][7];
        float ivr = siv[c][0], ivi = siv[c][1];
        float2 vi = ((const float2*)mod_i)[(c * 16 + r) * 512 + m];
        float ar = vi.x + t0r, ai = vi.y + t0i;
        float r1 = ai * t1i - ar * t1r;
        float i1 = ar * t1i + ai * t1r;
        sir += i1 * ivi - r1 * ivr;
        sii += r1 * ivi + i1 * ivr;
        float2 vj = ((const float2*)mod_j)[(c * 16 + r) * 512 + m];
        float br2 = vj.x + t2r, bi2 = vj.y + t2i;
        float r2 = bi2 * t3i - br2 * t3r;
        float i2 = br2 * t3i + bi2 * t3r;
        float idn = 1.f / (r2 * r2 + i2 * i2);
        sjr += (ivr * r2 + ivi * i2) * idn;
        sji += (ivr * i2 - ivi * r2) * idn;
    }
    g_mi[b][0][r][m] = sir; g_mi[b][1][r][m] = sii;
    g_mj[b][0][r][m] = sjr; g_mj[b][1][r][m] = sji;
}

// ---------------- k_mod: per (b, 16-m tile); mj cached in smem once ----------------
// dynamic smem: smj (interleaved [16][512][2] = 16384 f) + smi ([16][16][2] = 512 f)
__global__ void k_mod() {
    extern __shared__ float sm[];
    float* smj = sm;            // [r][n][2]
    float* smi = sm + 16384;    // [r][ml][2]
    const int blk = blockIdx.x, b = blk >> 5, mt0 = (blk & 31) * 16;
    const int tid = threadIdx.x;
    const float* mjb = (const float*)g_mj[b];   // [2][16][512]
    for (int i = tid; i < 8192; i += 256) {
        float re = mjb[i], im = mjb[8192 + i];
        smj[2 * i] = re; smj[2 * i + 1] = im;
    }
    for (int i = tid; i < 256; i += 256) {
        int r = i >> 4, ml = i & 15;
        smi[2 * i]     = g_mi[b][0][r][mt0 + ml];
        smi[2 * i + 1] = g_mi[b][1][r][mt0 + ml];
    }
    __syncthreads();

    float s1 = 0.f, s2 = 0.f;
    #pragma unroll
    for (int hh = 0; hh < 2; ++hh) {
        const int n = hh * 256 + tid;
        float cr[16], ci[16];
        #pragma unroll
        for (int ml = 0; ml < 16; ++ml) { cr[ml] = 0.f; ci[ml] = 0.f; }
        #pragma unroll
        for (int r = 0; r < 16; ++r) {
            float2 bj = *(const float2*)&smj[(r * 512 + n) * 2];
            const float4* ai4 = (const float4*)&smi[r * 32];
            #pragma unroll
            for (int mp = 0; mp < 8; ++mp) {
                float4 a2 = ai4[mp];
                cr[2 * mp]     += a2.x * bj.x - a2.y * bj.y;
                ci[2 * mp]     += a2.x * bj.y + a2.y * bj.x;
                cr[2 * mp + 1] += a2.z * bj.x - a2.w * bj.y;
                ci[2 * mp + 1] += a2.z * bj.y + a2.w * bj.x;
            }
        }
        #pragma unroll
        for (int ml = 0; ml < 16; ++ml) {
            g_mod[b][0][(mt0 + ml) * 512 + n] = cr[ml];
            g_mod[b][1][(mt0 + ml) * 512 + n] = ci[ml];
            s1 += cr[ml]; s2 += cr[ml] * cr[ml];
        }
    }
    __shared__ float rs1[256], rs2[256];
    rs1[tid] = s1; rs2[tid] = s2; __syncthreads();
    for (int off = 128; off; off >>= 1) {
        if (tid < off) { rs1[tid] += rs1[tid + off]; rs2[tid] += rs2[tid + off]; }
        __syncthreads();
    }
    if (tid == 0) { g_part[b][blk & 31][0] = rs1[0]; g_part[b][blk & 31][1] = rs2[0]; }
}

// ---------------- k_stats: 8 blocks x 32 threads, warp reduce ----------------
__global__ void k_stats() {
    int b = blockIdx.x, t = threadIdx.x;
    float s1 = g_part[b][t][0], s2 = g_part[b][t][1];
    #pragma unroll
    for (int off = 16; off; off >>= 1) {
        s1 += __shfl_down_sync(0xffffffffu, s1, off);
        s2 += __shfl_down_sync(0xffffffffu, s2, off);
    }
    if (t == 0) { g_stats[b][0] = s1; g_stats[b][1] = s2; }
}

// ---------------- k_packA0: Wi -> A0 = [Wir^T | Wii^T] (hi only) ----------------
__global__ void k_packA0(const float* __restrict__ Wi) {
    int mt = blockIdx.x * 32, pt = blockIdx.y * 32;
    __shared__ float sr[32][33], si[32][33];
    int t = threadIdx.x;
    #pragma unroll
    for (int rr = 0; rr < 4; ++rr) {
        int e = t + 256 * rr, ml = e >> 5, pl = e & 31;
        float2 v = ((const float2*)Wi)[(mt + ml) * 512 + pt + pl];
        sr[ml][pl] = v.x; si[ml][pl] = v.y;
    }
    __syncthreads();
    int pl = t >> 3, m4 = (t & 7) * 4;
    uint32_t hr[2], hi_[2];
    #pragma unroll
    for (int g = 0; g < 2; ++g) {
        hr[g]  = h2_rn(sr[m4 + 2 * g][pl], sr[m4 + 2 * g + 1][pl]);
        hi_[g] = h2_rn(si[m4 + 2 * g][pl], si[m4 + 2 * g + 1][pl]);
    }
    size_t row = (size_t)(pt + pl) * 1024;
    int col = mt + m4;
    *(uint2*)(g_A0h + row + col)       = make_uint2(hr[0], hr[1]);
    *(uint2*)(g_A0h + row + 512 + col) = make_uint2(hi_[0], hi_[1]);
}

// ---------------- k_packB1: Wj -> B1 (hi only), rows 2n' = [Wjr | -Wji], 2n'+1 = [Wji | Wjr] ----
__global__ void k_packB1(const float* __restrict__ Wj) {
    int nt = blockIdx.x * 32, pt = blockIdx.y * 32;
    __shared__ float sr[32][33], si[32][33];
    int t = threadIdx.x;
    #pragma unroll
    for (int rr = 0; rr < 4; ++rr) {
        int e = t + 256 * rr, nl = e >> 5, pl = e & 31;
        float2 v = ((const float2*)Wj)[(nt + nl) * 512 + pt + pl];
        sr[nl][pl] = v.x; si[nl][pl] = v.y;
    }
    __syncthreads();
    int pl = t >> 3, m4 = (t & 7) * 4;
    uint32_t hr[2], hi_[2];
    #pragma unroll
    for (int g = 0; g < 2; ++g) {
        hr[g]  = h2_rn(sr[m4 + 2 * g][pl], sr[m4 + 2 * g + 1][pl]);
        hi_[g] = h2_rn(si[m4 + 2 * g][pl], si[m4 + 2 * g + 1][pl]);
    }
    int np = pt + pl;
    size_t row_r = (size_t)(2 * np) * 1024;
    size_t row_i = (size_t)(2 * np + 1) * 1024;
    int col = nt + m4;
    *(uint2*)(g_B1h + row_r + col)       = make_uint2(hr[0], hr[1]);
    *(uint2*)(g_B1h + row_r + 512 + col) = make_uint2(hi_[0] ^ 0x80008000u, hi_[1] ^ 0x80008000u);
    *(uint2*)(g_B1h + row_i + col)       = make_uint2(hi_[0], hi_[1]);
    *(uint2*)(g_B1h + row_i + 512 + col) = make_uint2(hr[0], hr[1]);
}

// ---------------- k_packB0: wd0 -> B0 block matrix (hi only) per batch ----------------
__global__ void k_packB0(const float* __restrict__ wb) {
    int mt = blockIdx.x * 32, nt = blockIdx.y * 32, b = blockIdx.z;
    float s1 = g_stats[b][0], s2 = g_stats[b][1];
    float mean = s1 * (1.f / 262144.f);
    float var = (s2 - s1 * mean) * (1.f / 262143.f);
    float istd = rsqrtf(var);
    __shared__ float wr[32][33], wi[32][33];
    int t = threadIdx.x;
    #pragma unroll
    for (int rr = 0; rr < 4; ++rr) {
        int e = t + 256 * rr, ml = e >> 5, nl = e & 31;
        int idx = (mt + ml) * 512 + nt + nl;
        float2 w = ((const float2*)wb)[idx];
        wr[ml][nl] = w.x * (1.f + (g_mod[b][0][idx] - mean) * istd);
        wi[ml][nl] = w.y * (1.f + g_mod[b][1][idx]);
    }
    __syncthreads();
    int nl = t >> 3, m4 = (t & 7) * 4;
    uint32_t hr[2], hi_[2];
    #pragma unroll
    for (int g = 0; g < 2; ++g) {
        hr[g]  = h2_rn(wr[m4 + 2 * g][nl], wr[m4 + 2 * g + 1][nl]);
        hi_[g] = h2_rn(wi[m4 + 2 * g][nl], wi[m4 + 2 * g + 1][nl]);
    }
    size_t row_r = (size_t)(nt + nl) * 1024;
    size_t row_i = (size_t)(512 + nt + nl) * 1024;
    int col = mt + m4;
    half* Bh = g_B0h[b];
    *(uint2*)(Bh + row_r + col)       = make_uint2(hr[0], hr[1]);
    *(uint2*)(Bh + row_r + 512 + col) = make_uint2(hi_[0] ^ 0x80008000u, hi_[1] ^ 0x80008000u);
    *(uint2*)(Bh + row_i + col)       = make_uint2(hi_[0], hi_[1]);
    *(uint2*)(Bh + row_i + 512 + col) = make_uint2(hr[0], hr[1]);
}

// ---------------- mma.sync GEMM: 1 pass per stage, buffer 32KB {Ah@0, Bh@16K} ----------------
__device__ __forceinline__ void prefetch_chunk(
    const half* __restrict__ Ah, const half* __restrict__ Bh,
    int arow, int brow, int kb, uint32_t sdst, int tid) {
    const half* srcs[2] = { Ah, Bh };
    const int rows0[2] = { arow, brow };
    #pragma unroll
    for (int arr = 0; arr < 2; ++arr) {
        #pragma unroll
        for (int i = 0; i < 4; ++i) {
            int u = tid + 256 * i, row = u >> 3, seg = u & 7;
            const half* g = srcs[arr] + (size_t)(rows0[arr] + row) * 1024 + kb + seg * 8;
            uint32_t s = sdst + arr * 16384 + SWZ(row * 128 + seg * 16);
            CP_ASYNC16(s, g);
        }
    }
    CP_COMMIT();
}

template<int STAGE>
__global__ void __launch_bounds__(256, 2) k_mma(float* __restrict__ gout) {
    extern __shared__ __align__(1024) char smem[];
    const int tid = threadIdx.x, wid = tid >> 5, lane = tid & 31;
    const int wm = wid >> 1, wn = wid & 1;
    const int b = blockIdx.z, My = blockIdx.y, Nx = blockIdx.x;
    const half *Ah, *Bh;
    if (STAGE == 0) { Ah = g_A0h;    Bh = g_B0h[b]; }
    else            { Ah = g_A1h[b]; Bh = g_B1h; }
    const int arow = My * 128, brow = Nx * 128;
    const uint32_t sb = smem_u32(smem);

    float c[2][8][4];
    #pragma unroll
    for (int mt = 0; mt < 2; ++mt)
        #pragma unroll
        for (int nt = 0; nt < 8; ++nt)
            #pragma unroll
            for (int q = 0; q < 4; ++q) c[mt][nt][q] = 0.f;

    prefetch_chunk(Ah, Bh, arow, brow, 0, sb, tid);

    for (int ch = 0; ch < 16; ++ch) {
        const uint32_t sbuf = sb + (ch & 1) * 32768;
        if (ch + 1 < 16) {
            prefetch_chunk(Ah, Bh, arow, brow, (ch + 1) * 64,
                           sb + ((ch + 1) & 1) * 32768, tid);
            CP_WAIT(1);
        } else {
            CP_WAIT(0);
        }
        __syncthreads();

        const uint32_t sA = sbuf, sB = sbuf + 16384;
        #pragma unroll
        for (int ks = 0; ks < 4; ++ks) {
            uint32_t ah[2][4], bh[8][2];
            #pragma unroll
            for (int mt = 0; mt < 2; ++mt) {
                int row = wm * 32 + mt * 16 + (lane & 15);
                uint32_t off = SWZ(row * 128 + ks * 32 + (lane >> 4) * 16);
                LDSM_X4(ah[mt][0], ah[mt][1], ah[mt][2], ah[mt][3], sA + off);
            }
            #pragma unroll
            for (int ntp = 0; ntp < 4; ++ntp) {
                int row = wn * 64 + ntp * 16 + (lane >> 4) * 8 + (lane & 7);
                uint32_t off = SWZ(row * 128 + ks * 32 + ((lane >> 3) & 1) * 16);
                LDSM_X4(bh[2 * ntp][0], bh[2 * ntp][1], bh[2 * ntp + 1][0], bh[2 * ntp + 1][1], sB + off);
            }
            #pragma unroll
            for (int mt = 0; mt < 2; ++mt)
                #pragma unroll
                for (int nt = 0; nt < 8; ++nt)
                    MMA16816(c[mt][nt], ah[mt], bh[nt]);
        }
        __syncthreads();
    }

    // ---------------- epilogue ----------------
    const int r0 = My * 128 + wm * 32 + (lane >> 2);
    if (STAGE == 0) {
        half* dh = g_A1h[b];
        #pragma unroll
        for (int mt = 0; mt < 2; ++mt)
            #pragma unroll
            for (int nt = 0; nt < 8; ++nt) {
                int row = r0 + mt * 16;
                int col = Nx * 128 + wn * 64 + nt * 8 + 2 * (lane & 3);
                *(uint32_t*)(dh + (size_t)row * 1024 + col)       = h2_rn(c[mt][nt][0], c[mt][nt][1]);
                *(uint32_t*)(dh + (size_t)(row + 8) * 1024 + col) = h2_rn(c[mt][nt][2], c[mt][nt][3]);
            }
    } else {
        const float A_ = g_scal[0], B_ = g_scal[1], K_ = g_scal[2];
        float* O = gout + b * PL;
        #pragma unroll
        for (int mt = 0; mt < 2; ++mt)
            #pragma unroll
            for (int nt = 0; nt < 8; ++nt) {
                int row = r0 + mt * 16;
                int np = Nx * 64 + wn * 32 + nt * 4 + (lane & 3);
                O[(size_t)row * 512 + np] =
                    fmaf(c[mt][nt][1], A_, fmaf(c[mt][nt][0], B_, K_));
                O[(size_t)(row + 8) * 512 + np] =
                    fmaf(c[mt][nt][3], A_, fmaf(c[mt][nt][2], B_, K_));
            }
    }
}

// ---------------- launch ----------------
extern "C" void kernel_launch(void* const* d_in, const int* in_sizes, int n_in,
                              void* d_out, int out_size) {
    (void)in_sizes; (void)n_in; (void)out_size;
    const float* x   = (const float*)d_in[0];
    const float* Wi  = (const float*)d_in[1];
    const float* Wj  = (const float*)d_in[2];
    const float* Wb  = (const float*)d_in[3];
    const float* td  = (const float*)d_in[6];
    const float* rd  = (const float*)d_in[7];
    const float* mi  = (const float*)d_in[8];
    const float* mj  = (const float*)d_in[9];
    const float* inv = (const float*)d_in[10];
    const float* mt  = (const float*)d_in[11];
    float* out = (float*)d_out;

    const int SMEM_G = 2 * 32768;      // 64 KB GEMM, 2 CTAs/SM
    const int SMEM_MOD = 16896 * 4;    // 67.6 KB for k_mod
    cudaFuncSetAttribute(k_mma<0>, cudaFuncAttributeMaxDynamicSharedMemorySize, SMEM_G);
    cudaFuncSetAttribute(k_mma<1>, cudaFuncAttributeMaxDynamicSharedMemorySize, SMEM_G);
    cudaFuncSetAttribute(k_mod, cudaFuncAttributeMaxDynamicSharedMemorySize, SMEM_MOD);

    k_setup<<<1, 256>>>(x, mt, td, rd);
    k_mimj<<<128, 512>>>(mi, mj, inv);
    k_mod<<<256, 256, SMEM_MOD>>>();
    k_stats<<<8, 32>>>();
    k_packA0<<<dim3(16, 16), 256>>>(Wi);
    k_packB1<<<dim3(16, 16), 256>>>(Wj);
    k_packB0<<<dim3(16, 16, 8), 256>>>(Wb);
    dim3 grid(8, 4, 8);
    k_mma<0><<<grid, 256, SMEM_G>>>(nullptr);
    k_mma<1><<<grid, 256, SMEM_G>>>(out);
}

// round 15
// speedup vs baseline: 1.8987x; 1.0197x over previous
#include <cuda_runtime.h>
#include <cuda_fp16.h>
#include <cstdint>

#define PL (512*512)
typedef unsigned long long u64;

// ---------------- scratch ----------------
__device__ float g_part[8][32][2];
__device__ float g_mi[8][2][16][512];
__device__ float g_mj[8][2][16][512];
__device__ float g_mod[8][2][PL];
__device__ half g_A0h[512 * 1024];       // Wi^T pack (hi only): [m'][k2 = m | 512+m]
__device__ half g_B0h[8][1024 * 1024];   // wd0 block matrix (hi only)
__device__ half g_A1h[8][512 * 1024];    // stage-0 out (hi only): [m'][k2' = n | 512+n]
__device__ half g_B1h[1024 * 1024];      // Wj block matrix, rows 2n'/2n'+1 (hi only)

#define SWZ(x) ((x) ^ (((x) >> 3) & 0x70))

__device__ __forceinline__ uint32_t smem_u32(const void* p) {
    uint32_t a;
    asm("{ .reg .u64 t; cvta.to.shared.u64 t, %1; cvt.u32.u64 %0, t; }" : "=r"(a) : "l"(p));
    return a;
}
__device__ __forceinline__ uint32_t h2_rn(float v0, float v1) {
    __half2 h = __floats2half2_rn(v0, v1);
    return *(uint32_t*)&h;
}
#define LDSM_X4(r0, r1, r2, r3, a) \
    asm volatile("ldmatrix.sync.aligned.m8n8.x4.shared.b16 {%0,%1,%2,%3}, [%4];" \
        : "=r"(r0), "=r"(r1), "=r"(r2), "=r"(r3) : "r"(a))
#define MMA16816(c, a, b) \
    asm volatile("mma.sync.aligned.m16n8k16.row.col.f32.f16.f16.f32 " \
        "{%0,%1,%2,%3}, {%4,%5,%6,%7}, {%8,%9}, {%0,%1,%2,%3};" \
        : "+f"((c)[0]), "+f"((c)[1]), "+f"((c)[2]), "+f"((c)[3]) \
        : "r"((a)[0]), "r"((a)[1]), "r"((a)[2]), "r"((a)[3]), "r"((b)[0]), "r"((b)[1]))
#define CP_ASYNC16(s, g) \
    asm volatile("cp.async.cg.shared.global [%0], [%1], 16;" :: "r"(s), "l"(g) : "memory")
#define CP_COMMIT()  asm volatile("cp.async.commit_group;" ::: "memory")
#define CP_WAIT(n)   asm volatile("cp.async.wait_group %0;" :: "n"(n) : "memory")

// ---------------- k_prep: fused mimj (128 blk) + packA0 (256 blk) + packB1 (256 blk) ----------------
__global__ void k_prep(const float* __restrict__ x,  const float* __restrict__ mt,
                       const float* __restrict__ mod_i, const float* __restrict__ mod_j,
                       const float* __restrict__ inv,
                       const float* __restrict__ Wi, const float* __restrict__ Wj) {
    __shared__ float sr[32][33], si[32][33];
    const int blk = blockIdx.x, tid = threadIdx.x;

    if (blk < 128) {
        // ---- mimj: b = blk>>4, r = blk&15, 256 threads x 2 m ----
        float* st  = &sr[0][0];    // [16][8]: st[c2*8 + k*2+e]
        float* siv = &si[0][0];    // [16][2]
        const int b = blk >> 4, r = blk & 15;
        if (tid < 128) {
            int e = tid & 1, c2 = (tid >> 1) & 15, k = (tid >> 5) & 3;
            float s = 0.f;
            #pragma unroll
            for (int c = 0; c < 16; ++c)
                s += x[b * 16 + c] * mt[(k * 16 + c) * 32 + c2 * 2 + e];
            st[c2 * 8 + k * 2 + e] = s;
        } else if (tid < 160) {
            int q = tid - 128;
            siv[q] = inv[q];
        }
        __syncthreads();
        #pragma unroll
        for (int mm = 0; mm < 2; ++mm) {
            const int m = tid + mm * 256;
            float sir = 0.f, sii = 0.f, sjr = 0.f, sji = 0.f;
            #pragma unroll 4
            for (int c = 0; c < 16; ++c) {
                float t0r = st[c * 8 + 0], t0i = st[c * 8 + 1];
                float t1r = st[c * 8 + 2], t1i = st[c * 8 + 3];
                float t2r = st[c * 8 + 4], t2i = st[c * 8 + 5];
                float t3r = st[c * 8 + 6], t3i = st[c * 8 + 7];
                float ivr = siv[c * 2], ivi = siv[c * 2 + 1];
                float2 vi = ((const float2*)mod_i)[(c * 16 + r) * 512 + m];
                float ar = vi.x + t0r, ai = vi.y + t0i;
                float r1 = ai * t1i - ar * t1r;
                float i1 = ar * t1i + ai * t1r;
                sir += i1 * ivi - r1 * ivr;
                sii += r1 * ivi + i1 * ivr;
                float2 vj = ((const float2*)mod_j)[(c * 16 + r) * 512 + m];
                float br2 = vj.x + t2r, bi2 = vj.y + t2i;
                float r2 = bi2 * t3i - br2 * t3r;
                float i2 = br2 * t3i + bi2 * t3r;
                float idn = 1.f / (r2 * r2 + i2 * i2);
                sjr += (ivr * r2 + ivi * i2) * idn;
                sji += (ivr * i2 - ivi * r2) * idn;
            }
            g_mi[b][0][r][m] = sir; g_mi[b][1][r][m] = sii;
            g_mj[b][0][r][m] = sjr; g_mj[b][1][r][m] = sji;
        }
        return;
    }

    if (blk < 384) {
        // ---- packA0: Wi -> [Wir^T | Wii^T] ----
        const int idx = blk - 128;
        const int mtile = (idx & 15) * 32, pt = (idx >> 4) * 32;
        #pragma unroll
        for (int rr = 0; rr < 4; ++rr) {
            int e = tid + 256 * rr, ml = e >> 5, pl = e & 31;
            float2 v = ((const float2*)Wi)[(mtile + ml) * 512 + pt + pl];
            sr[ml][pl] = v.x; si[ml][pl] = v.y;
        }
        __syncthreads();
        int pl = tid >> 3, m4 = (tid & 7) * 4;
        uint32_t hr[2], hi_[2];
        #pragma unroll
        for (int g = 0; g < 2; ++g) {
            hr[g]  = h2_rn(sr[m4 + 2 * g][pl], sr[m4 + 2 * g + 1][pl]);
            hi_[g] = h2_rn(si[m4 + 2 * g][pl], si[m4 + 2 * g + 1][pl]);
        }
        size_t row = (size_t)(pt + pl) * 1024;
        int col = mtile + m4;
        *(uint2*)(g_A0h + row + col)       = make_uint2(hr[0], hr[1]);
        *(uint2*)(g_A0h + row + 512 + col) = make_uint2(hi_[0], hi_[1]);
        return;
    }

    // ---- packB1: Wj -> rows 2n' = [Wjr | -Wji], 2n'+1 = [Wji | Wjr] ----
    {
        const int idx = blk - 384;
        const int nt = (idx & 15) * 32, pt = (idx >> 4) * 32;
        #pragma unroll
        for (int rr = 0; rr < 4; ++rr) {
            int e = tid + 256 * rr, nl = e >> 5, pl = e & 31;
            float2 v = ((const float2*)Wj)[(nt + nl) * 512 + pt + pl];
            sr[nl][pl] = v.x; si[nl][pl] = v.y;
        }
        __syncthreads();
        int pl = tid >> 3, m4 = (tid & 7) * 4;
        uint32_t hr[2], hi_[2];
        #pragma unroll
        for (int g = 0; g < 2; ++g) {
            hr[g]  = h2_rn(sr[m4 + 2 * g][pl], sr[m4 + 2 * g + 1][pl]);
            hi_[g] = h2_rn(si[m4 + 2 * g][pl], si[m4 + 2 * g + 1][pl]);
        }
        int np = pt + pl;
        size_t row_r = (size_t)(2 * np) * 1024;
        size_t row_i = (size_t)(2 * np + 1) * 1024;
        int col = nt + m4;
        *(uint2*)(g_B1h + row_r + col)       = make_uint2(hr[0], hr[1]);
        *(uint2*)(g_B1h + row_r + 512 + col) = make_uint2(hi_[0] ^ 0x80008000u, hi_[1] ^ 0x80008000u);
        *(uint2*)(g_B1h + row_i + col)       = make_uint2(hi_[0], hi_[1]);
        *(uint2*)(g_B1h + row_i + 512 + col) = make_uint2(hr[0], hr[1]);
    }
}

// ---------------- k_mod: per (b, 16-m tile); mj cached in smem once ----------------
__global__ void k_mod() {
    extern __shared__ float sm[];
    float* smj = sm;            // [r][n][2]
    float* smi = sm + 16384;    // [r][ml][2]
    const int blk = blockIdx.x, b = blk >> 5, mt0 = (blk & 31) * 16;
    const int tid = threadIdx.x;
    const float* mjb = (const float*)g_mj[b];
    for (int i = tid; i < 8192; i += 256) {
        float re = mjb[i], im = mjb[8192 + i];
        smj[2 * i] = re; smj[2 * i + 1] = im;
    }
    if (tid < 256) {
        int r = tid >> 4, ml = tid & 15;
        smi[2 * tid]     = g_mi[b][0][r][mt0 + ml];
        smi[2 * tid + 1] = g_mi[b][1][r][mt0 + ml];
    }
    __syncthreads();

    float s1 = 0.f, s2 = 0.f;
    #pragma unroll
    for (int hh = 0; hh < 2; ++hh) {
        const int n = hh * 256 + tid;
        float cr[16], ci[16];
        #pragma unroll
        for (int ml = 0; ml < 16; ++ml) { cr[ml] = 0.f; ci[ml] = 0.f; }
        #pragma unroll
        for (int r = 0; r < 16; ++r) {
            float2 bj = *(const float2*)&smj[(r * 512 + n) * 2];
            const float4* ai4 = (const float4*)&smi[r * 32];
            #pragma unroll
            for (int mp = 0; mp < 8; ++mp) {
                float4 a2 = ai4[mp];
                cr[2 * mp]     += a2.x * bj.x - a2.y * bj.y;
                ci[2 * mp]     += a2.x * bj.y + a2.y * bj.x;
                cr[2 * mp + 1] += a2.z * bj.x - a2.w * bj.y;
                ci[2 * mp + 1] += a2.z * bj.y + a2.w * bj.x;
            }
        }
        #pragma unroll
        for (int ml = 0; ml < 16; ++ml) {
            g_mod[b][0][(mt0 + ml) * 512 + n] = cr[ml];
            g_mod[b][1][(mt0 + ml) * 512 + n] = ci[ml];
            s1 += cr[ml]; s2 += cr[ml] * cr[ml];
        }
    }
    __shared__ float rs1[256], rs2[256];
    rs1[tid] = s1; rs2[tid] = s2; __syncthreads();
    for (int off = 128; off; off >>= 1) {
        if (tid < off) { rs1[tid] += rs1[tid + off]; rs2[tid] += rs2[tid + off]; }
        __syncthreads();
    }
    if (tid == 0) { g_part[b][blk & 31][0] = rs1[0]; g_part[b][blk & 31][1] = rs2[0]; }
}

// ---------------- k_packB0: inline stats + wd0 -> B0 block matrix (hi only) ----------------
__global__ void k_packB0(const float* __restrict__ wb) {
    int mt = blockIdx.x * 32, nt = blockIdx.y * 32, b = blockIdx.z;
    __shared__ float s_mean, s_istd;
    const int t = threadIdx.x;
    if (t < 32) {
        float s1 = g_part[b][t][0], s2 = g_part[b][t][1];
        #pragma unroll
        for (int off = 16; off; off >>= 1) {
            s1 += __shfl_down_sync(0xffffffffu, s1, off);
            s2 += __shfl_down_sync(0xffffffffu, s2, off);
        }
        if (t == 0) {
            float mean = s1 * (1.f / 262144.f);
            float var = (s2 - s1 * mean) * (1.f / 262143.f);
            s_mean = mean; s_istd = rsqrtf(var);
        }
    }
    __syncthreads();
    const float mean = s_mean, istd = s_istd;
    __shared__ float wr[32][33], wi[32][33];
    #pragma unroll
    for (int rr = 0; rr < 4; ++rr) {
        int e = t + 256 * rr, ml = e >> 5, nl = e & 31;
        int idx = (mt + ml) * 512 + nt + nl;
        float2 w = ((const float2*)wb)[idx];
        wr[ml][nl] = w.x * (1.f + (g_mod[b][0][idx] - mean) * istd);
        wi[ml][nl] = w.y * (1.f + g_mod[b][1][idx]);
    }
    __syncthreads();
    int nl = t >> 3, m4 = (t & 7) * 4;
    uint32_t hr[2], hi_[2];
    #pragma unroll
    for (int g = 0; g < 2; ++g) {
        hr[g]  = h2_rn(wr[m4 + 2 * g][nl], wr[m4 + 2 * g + 1][nl]);
        hi_[g] = h2_rn(wi[m4 + 2 * g][nl], wi[m4 + 2 * g + 1][nl]);
    }
    size_t row_r = (size_t)(nt + nl) * 1024;
    size_t row_i = (size_t)(512 + nt + nl) * 1024;
    int col = mt + m4;
    half* Bh = g_B0h[b];
    *(uint2*)(Bh + row_r + col)       = make_uint2(hr[0], hr[1]);
    *(uint2*)(Bh + row_r + 512 + col) = make_uint2(hi_[0] ^ 0x80008000u, hi_[1] ^ 0x80008000u);
    *(uint2*)(Bh + row_i + col)       = make_uint2(hi_[0], hi_[1]);
    *(uint2*)(Bh + row_i + 512 + col) = make_uint2(hr[0], hr[1]);
}

// ---------------- mma.sync GEMM: 1 pass per stage, buffer 32KB {Ah@0, Bh@16K} ----------------
__device__ __forceinline__ void prefetch_chunk(
    const half* __restrict__ Ah, const half* __restrict__ Bh,
    int arow, int brow, int kb, uint32_t sdst, int tid) {
    const half* srcs[2] = { Ah, Bh };
    const int rows0[2] = { arow, brow };
    #pragma unroll
    for (int arr = 0; arr < 2; ++arr) {
        #pragma unroll
        for (int i = 0; i < 4; ++i) {
            int u = tid + 256 * i, row = u >> 3, seg = u & 7;
            const half* g = srcs[arr] + (size_t)(rows0[arr] + row) * 1024 + kb + seg * 8;
            uint32_t s = sdst + arr * 16384 + SWZ(row * 128 + seg * 16);
            CP_ASYNC16(s, g);
        }
    }
    CP_COMMIT();
}

template<int STAGE>
__global__ void __launch_bounds__(256, 2) k_mma(float* __restrict__ gout,
                                                const float* __restrict__ td,
                                                const float* __restrict__ rd) {
    extern __shared__ __align__(1024) char smem[];
    const int tid = threadIdx.x, wid = tid >> 5, lane = tid & 31;
    const int wm = wid >> 1, wn = wid & 1;
    const int b = blockIdx.z, My = blockIdx.y, Nx = blockIdx.x;
    const half *Ah, *Bh;
    if (STAGE == 0) { Ah = g_A0h;    Bh = g_B0h[b]; }
    else            { Ah = g_A1h[b]; Bh = g_B1h; }
    const int arow = My * 128, brow = Nx * 128;
    const uint32_t sb = smem_u32(smem);

    float c[2][8][4];
    #pragma unroll
    for (int mt = 0; mt < 2; ++mt)
        #pragma unroll
        for (int nt = 0; nt < 8; ++nt)
            #pragma unroll
            for (int q = 0; q < 4; ++q) c[mt][nt][q] = 0.f;

    prefetch_chunk(Ah, Bh, arow, brow, 0, sb, tid);

    for (int ch = 0; ch < 16; ++ch) {
        const uint32_t sbuf = sb + (ch & 1) * 32768;
        if (ch + 1 < 16) {
            prefetch_chunk(Ah, Bh, arow, brow, (ch + 1) * 64,
                           sb + ((ch + 1) & 1) * 32768, tid);
            CP_WAIT(1);
        } else {
            CP_WAIT(0);
        }
        __syncthreads();

        const uint32_t sA = sbuf, sB = sbuf + 16384;
        #pragma unroll
        for (int ks = 0; ks < 4; ++ks) {
            uint32_t ah[2][4], bh[8][2];
            #pragma unroll
            for (int mt = 0; mt < 2; ++mt) {
                int row = wm * 32 + mt * 16 + (lane & 15);
                uint32_t off = SWZ(row * 128 + ks * 32 + (lane >> 4) * 16);
                LDSM_X4(ah[mt][0], ah[mt][1], ah[mt][2], ah[mt][3], sA + off);
            }
            #pragma unroll
            for (int ntp = 0; ntp < 4; ++ntp) {
                int row = wn * 64 + ntp * 16 + (lane >> 4) * 8 + (lane & 7);
                uint32_t off = SWZ(row * 128 + ks * 32 + ((lane >> 3) & 1) * 16);
                LDSM_X4(bh[2 * ntp][0], bh[2 * ntp][1], bh[2 * ntp + 1][0], bh[2 * ntp + 1][1], sB + off);
            }
            #pragma unroll
            for (int mt = 0; mt < 2; ++mt)
                #pragma unroll
                for (int nt = 0; nt < 8; ++nt)
                    MMA16816(c[mt][nt], ah[mt], bh[nt]);
        }
        __syncthreads();
    }

    // ---------------- epilogue ----------------
    const int r0 = My * 128 + wm * 32 + (lane >> 2);
    if (STAGE == 0) {
        half* dh = g_A1h[b];
        #pragma unroll
        for (int mt = 0; mt < 2; ++mt)
            #pragma unroll
            for (int nt = 0; nt < 8; ++nt) {
                int row = r0 + mt * 16;
                int col = Nx * 128 + wn * 64 + nt * 8 + 2 * (lane & 3);
                *(uint32_t*)(dh + (size_t)row * 1024 + col)       = h2_rn(c[mt][nt][0], c[mt][nt][1]);
                *(uint32_t*)(dh + (size_t)(row + 8) * 1024 + col) = h2_rn(c[mt][nt][2], c[mt][nt][3]);
            }
    } else {
        float A_ = 0.f, B_ = 0.f, K_ = 0.f;
        #pragma unroll
        for (int cc = 0; cc < 16; ++cc) {
            float rr = rd[2 * cc], ri = rd[2 * cc + 1];
            float tr = td[2 * cc], ti = td[2 * cc + 1];
            A_ += ri; B_ -= rr; K_ += ti * ri - tr * rr;
        }
        float* O = gout + b * PL;
        #pragma unroll
        for (int mt = 0; mt < 2; ++mt)
            #pragma unroll
            for (int nt = 0; nt < 8; ++nt) {
                int row = r0 + mt * 16;
                int np = Nx * 64 + wn * 32 + nt * 4 + (lane & 3);
                O[(size_t)row * 512 + np] =
                    fmaf(c[mt][nt][1], A_, fmaf(c[mt][nt][0], B_, K_));
                O[(size_t)(row + 8) * 512 + np] =
                    fmaf(c[mt][nt][3], A_, fmaf(c[mt][nt][2], B_, K_));
            }
    }
}

// ---------------- launch ----------------
extern "C" void kernel_launch(void* const* d_in, const int* in_sizes, int n_in,
                              void* d_out, int out_size) {
    (void)in_sizes; (void)n_in; (void)out_size;
    const float* x   = (const float*)d_in[0];
    const float* Wi  = (const float*)d_in[1];
    const float* Wj  = (const float*)d_in[2];
    const float* Wb  = (const float*)d_in[3];
    const float* td  = (const float*)d_in[6];
    const float* rd  = (const float*)d_in[7];
    const float* mi  = (const float*)d_in[8];
    const float* mj  = (const float*)d_in[9];
    const float* inv = (const float*)d_in[10];
    const float* mt  = (const float*)d_in[11];
    float* out = (float*)d_out;

    const int SMEM_G = 2 * 32768;      // 64 KB GEMM, 2 CTAs/SM
    const int SMEM_MOD = 16896 * 4;    // 67.6 KB for k_mod
    cudaFuncSetAttribute(k_mma<0>, cudaFuncAttributeMaxDynamicSharedMemorySize, SMEM_G);
    cudaFuncSetAttribute(k_mma<1>, cudaFuncAttributeMaxDynamicSharedMemorySize, SMEM_G);
    cudaFuncSetAttribute(k_mod, cudaFuncAttributeMaxDynamicSharedMemorySize, SMEM_MOD);

    k_prep<<<640, 256>>>(x, mt, mi, mj, inv, Wi, Wj);
    k_mod<<<256, 256, SMEM_MOD>>>();
    k_packB0<<<dim3(16, 16, 8), 256>>>(Wb);
    dim3 grid(8, 4, 8);
    k_mma<0><<<grid, 256, SMEM_G>>>(nullptr, nullptr, nullptr);
    k_mma<1><<<grid, 256, SMEM_G>>>(out, td, rd);
}

// round 16
// speedup vs baseline: 1.9420x; 1.0228x over previous
#include <cuda_runtime.h>
#include <cuda_fp16.h>
#include <cstdint>

#define PL (512*512)
typedef unsigned long long u64;

// ---------------- scratch ----------------
__device__ float g_part[8][32][2];
__device__ float g_mi[8][2][16][512];
__device__ float g_mj[8][2][16][512];
__device__ uint32_t g_modh[8][PL];       // mod packed half2 (lo=re, hi=im)
__device__ half g_A0h[512 * 1024];       // Wi^T pack (hi only): [m'][k2 = m | 512+m]
__device__ half g_B0h[8][1024 * 1024];   // wd0 block matrix (hi only)
__device__ half g_A1h[8][512 * 1024];    // stage-0 out (hi only): [m'][k2' = n | 512+n]
__device__ half g_B1h[1024 * 1024];      // Wj block matrix, rows 2n'/2n'+1 (hi only)

#define SWZ(x) ((x) ^ (((x) >> 3) & 0x70))

__device__ __forceinline__ uint32_t smem_u32(const void* p) {
    uint32_t a;
    asm("{ .reg .u64 t; cvta.to.shared.u64 t, %1; cvt.u32.u64 %0, t; }" : "=r"(a) : "l"(p));
    return a;
}
__device__ __forceinline__ uint32_t h2_rn(float v0, float v1) {
    __half2 h = __floats2half2_rn(v0, v1);
    return *(uint32_t*)&h;
}
#define LDSM_X4(r0, r1, r2, r3, a) \
    asm volatile("ldmatrix.sync.aligned.m8n8.x4.shared.b16 {%0,%1,%2,%3}, [%4];" \
        : "=r"(r0), "=r"(r1), "=r"(r2), "=r"(r3) : "r"(a))
#define MMA16816(c, a, b) \
    asm volatile("mma.sync.aligned.m16n8k16.row.col.f32.f16.f16.f32 " \
        "{%0,%1,%2,%3}, {%4,%5,%6,%7}, {%8,%9}, {%0,%1,%2,%3};" \
        : "+f"((c)[0]), "+f"((c)[1]), "+f"((c)[2]), "+f"((c)[3]) \
        : "r"((a)[0]), "r"((a)[1]), "r"((a)[2]), "r"((a)[3]), "r"((b)[0]), "r"((b)[1]))
#define CP_ASYNC16(s, g) \
    asm volatile("cp.async.cg.shared.global [%0], [%1], 16;" :: "r"(s), "l"(g) : "memory")
#define CP_COMMIT()  asm volatile("cp.async.commit_group;" ::: "memory")
#define CP_WAIT(n)   asm volatile("cp.async.wait_group %0;" :: "n"(n) : "memory")

// ---------------- k_prep: fused mimj (128 blk) + packA0 (256 blk) + packB1 (256 blk) ----------------
__global__ void k_prep(const float* __restrict__ x,  const float* __restrict__ mt,
                       const float* __restrict__ mod_i, const float* __restrict__ mod_j,
                       const float* __restrict__ inv,
                       const float* __restrict__ Wi, const float* __restrict__ Wj) {
    __shared__ float sr[32][33], si[32][33];
    const int blk = blockIdx.x, tid = threadIdx.x;

    if (blk < 128) {
        float* st  = &sr[0][0];    // [16][8]
        float* siv = &si[0][0];    // [16][2]
        const int b = blk >> 4, r = blk & 15;
        if (tid < 128) {
            int e = tid & 1, c2 = (tid >> 1) & 15, k = (tid >> 5) & 3;
            float s = 0.f;
            #pragma unroll
            for (int c = 0; c < 16; ++c)
                s += x[b * 16 + c] * mt[(k * 16 + c) * 32 + c2 * 2 + e];
            st[c2 * 8 + k * 2 + e] = s;
        } else if (tid < 160) {
            int q = tid - 128;
            siv[q] = inv[q];
        }
        __syncthreads();
        #pragma unroll
        for (int mm = 0; mm < 2; ++mm) {
            const int m = tid + mm * 256;
            float sir = 0.f, sii = 0.f, sjr = 0.f, sji = 0.f;
            #pragma unroll 4
            for (int c = 0; c < 16; ++c) {
                float t0r = st[c * 8 + 0], t0i = st[c * 8 + 1];
                float t1r = st[c * 8 + 2], t1i = st[c * 8 + 3];
                float t2r = st[c * 8 + 4], t2i = st[c * 8 + 5];
                float t3r = st[c * 8 + 6], t3i = st[c * 8 + 7];
                float ivr = siv[c * 2], ivi = siv[c * 2 + 1];
                float2 vi = ((const float2*)mod_i)[(c * 16 + r) * 512 + m];
                float ar = vi.x + t0r, ai = vi.y + t0i;
                float r1 = ai * t1i - ar * t1r;
                float i1 = ar * t1i + ai * t1r;
                sir += i1 * ivi - r1 * ivr;
                sii += r1 * ivi + i1 * ivr;
                float2 vj = ((const float2*)mod_j)[(c * 16 + r) * 512 + m];
                float br2 = vj.x + t2r, bi2 = vj.y + t2i;
                float r2 = bi2 * t3i - br2 * t3r;
                float i2 = br2 * t3i + bi2 * t3r;
                float idn = 1.f / (r2 * r2 + i2 * i2);
                sjr += (ivr * r2 + ivi * i2) * idn;
                sji += (ivr * i2 - ivi * r2) * idn;
            }
            g_mi[b][0][r][m] = sir; g_mi[b][1][r][m] = sii;
            g_mj[b][0][r][m] = sjr; g_mj[b][1][r][m] = sji;
        }
        return;
    }

    if (blk < 384) {
        const int idx = blk - 128;
        const int mtile = (idx & 15) * 32, pt = (idx >> 4) * 32;
        #pragma unroll
        for (int rr = 0; rr < 4; ++rr) {
            int e = tid + 256 * rr, ml = e >> 5, pl = e & 31;
            float2 v = ((const float2*)Wi)[(mtile + ml) * 512 + pt + pl];
            sr[ml][pl] = v.x; si[ml][pl] = v.y;
        }
        __syncthreads();
        int pl = tid >> 3, m4 = (tid & 7) * 4;
        uint32_t hr[2], hi_[2];
        #pragma unroll
        for (int g = 0; g < 2; ++g) {
            hr[g]  = h2_rn(sr[m4 + 2 * g][pl], sr[m4 + 2 * g + 1][pl]);
            hi_[g] = h2_rn(si[m4 + 2 * g][pl], si[m4 + 2 * g + 1][pl]);
        }
        size_t row = (size_t)(pt + pl) * 1024;
        int col = mtile + m4;
        *(uint2*)(g_A0h + row + col)       = make_uint2(hr[0], hr[1]);
        *(uint2*)(g_A0h + row + 512 + col) = make_uint2(hi_[0], hi_[1]);
        return;
    }

    {
        const int idx = blk - 384;
        const int nt = (idx & 15) * 32, pt = (idx >> 4) * 32;
        #pragma unroll
        for (int rr = 0; rr < 4; ++rr) {
            int e = tid + 256 * rr, nl = e >> 5, pl = e & 31;
            float2 v = ((const float2*)Wj)[(nt + nl) * 512 + pt + pl];
            sr[nl][pl] = v.x; si[nl][pl] = v.y;
        }
        __syncthreads();
        int pl = tid >> 3, m4 = (tid & 7) * 4;
        uint32_t hr[2], hi_[2];
        #pragma unroll
        for (int g = 0; g < 2; ++g) {
            hr[g]  = h2_rn(sr[m4 + 2 * g][pl], sr[m4 + 2 * g + 1][pl]);
            hi_[g] = h2_rn(si[m4 + 2 * g][pl], si[m4 + 2 * g + 1][pl]);
        }
        int np = pt + pl;
        size_t row_r = (size_t)(2 * np) * 1024;
        size_t row_i = (size_t)(2 * np + 1) * 1024;
        int col = nt + m4;
        *(uint2*)(g_B1h + row_r + col)       = make_uint2(hr[0], hr[1]);
        *(uint2*)(g_B1h + row_r + 512 + col) = make_uint2(hi_[0] ^ 0x80008000u, hi_[1] ^ 0x80008000u);
        *(uint2*)(g_B1h + row_i + col)       = make_uint2(hi_[0], hi_[1]);
        *(uint2*)(g_B1h + row_i + 512 + col) = make_uint2(hr[0], hr[1]);
    }
}

// ---------------- k_mod: per (b, 16-m tile); mj cached in smem; writes mod as half2 ----------------
__global__ void k_mod() {
    extern __shared__ float sm[];
    float* smj = sm;            // [r][n][2]
    float* smi = sm + 16384;    // [r][ml][2]
    const int blk = blockIdx.x, b = blk >> 5, mt0 = (blk & 31) * 16;
    const int tid = threadIdx.x;
    const float* mjb = (const float*)g_mj[b];
    for (int i = tid; i < 8192; i += 256) {
        float re = mjb[i], im = mjb[8192 + i];
        smj[2 * i] = re; smj[2 * i + 1] = im;
    }
    if (tid < 256) {
        int r = tid >> 4, ml = tid & 15;
        smi[2 * tid]     = g_mi[b][0][r][mt0 + ml];
        smi[2 * tid + 1] = g_mi[b][1][r][mt0 + ml];
    }
    __syncthreads();

    float s1 = 0.f, s2 = 0.f;
    #pragma unroll
    for (int hh = 0; hh < 2; ++hh) {
        const int n = hh * 256 + tid;
        float cr[16], ci[16];
        #pragma unroll
        for (int ml = 0; ml < 16; ++ml) { cr[ml] = 0.f; ci[ml] = 0.f; }
        #pragma unroll
        for (int r = 0; r < 16; ++r) {
            float2 bj = *(const float2*)&smj[(r * 512 + n) * 2];
            const float4* ai4 = (const float4*)&smi[r * 32];
            #pragma unroll
            for (int mp = 0; mp < 8; ++mp) {
                float4 a2 = ai4[mp];
                cr[2 * mp]     += a2.x * bj.x - a2.y * bj.y;
                ci[2 * mp]     += a2.x * bj.y + a2.y * bj.x;
                cr[2 * mp + 1] += a2.z * bj.x - a2.w * bj.y;
                ci[2 * mp + 1] += a2.z * bj.y + a2.w * bj.x;
            }
        }
        #pragma unroll
        for (int ml = 0; ml < 16; ++ml) {
            g_modh[b][(mt0 + ml) * 512 + n] = h2_rn(cr[ml], ci[ml]);
            s1 += cr[ml]; s2 += cr[ml] * cr[ml];
        }
    }
    __shared__ float rs1[256], rs2[256];
    rs1[tid] = s1; rs2[tid] = s2; __syncthreads();
    for (int off = 128; off; off >>= 1) {
        if (tid < off) { rs1[tid] += rs1[tid + off]; rs2[tid] += rs2[tid + off]; }
        __syncthreads();
    }
    if (tid == 0) { g_part[b][blk & 31][0] = rs1[0]; g_part[b][blk & 31][1] = rs2[0]; }
}

// ---------------- k_packB0: inline stats + wd0 -> B0 block matrix (hi only), mod from half2 ----------------
__global__ void k_packB0(const float* __restrict__ wb) {
    int mt = blockIdx.x * 32, nt = blockIdx.y * 32, b = blockIdx.z;
    __shared__ float s_mean, s_istd;
    const int t = threadIdx.x;
    if (t < 32) {
        float s1 = g_part[b][t][0], s2 = g_part[b][t][1];
        #pragma unroll
        for (int off = 16; off; off >>= 1) {
            s1 += __shfl_down_sync(0xffffffffu, s1, off);
            s2 += __shfl_down_sync(0xffffffffu, s2, off);
        }
        if (t == 0) {
            float mean = s1 * (1.f / 262144.f);
            float var = (s2 - s1 * mean) * (1.f / 262143.f);
            s_mean = mean; s_istd = rsqrtf(var);
        }
    }
    __syncthreads();
    const float mean = s_mean, istd = s_istd;
    __shared__ float wr[32][33], wi[32][33];
    #pragma unroll
    for (int rr = 0; rr < 4; ++rr) {
        int e = t + 256 * rr, ml = e >> 5, nl = e & 31;
        int idx = (mt + ml) * 512 + nt + nl;
        float2 w = ((const float2*)wb)[idx];
        __half2 mo = *(const __half2*)&g_modh[b][idx];
        float mr = __half2float(__low2half(mo));
        float mi2 = __half2float(__high2half(mo));
        wr[ml][nl] = w.x * (1.f + (mr - mean) * istd);
        wi[ml][nl] = w.y * (1.f + mi2);
    }
    __syncthreads();
    int nl = t >> 3, m4 = (t & 7) * 4;
    uint32_t hr[2], hi_[2];
    #pragma unroll
    for (int g = 0; g < 2; ++g) {
        hr[g]  = h2_rn(wr[m4 + 2 * g][nl], wr[m4 + 2 * g + 1][nl]);
        hi_[g] = h2_rn(wi[m4 + 2 * g][nl], wi[m4 + 2 * g + 1][nl]);
    }
    size_t row_r = (size_t)(nt + nl) * 1024;
    size_t row_i = (size_t)(512 + nt + nl) * 1024;
    int col = mt + m4;
    half* Bh = g_B0h[b];
    *(uint2*)(Bh + row_r + col)       = make_uint2(hr[0], hr[1]);
    *(uint2*)(Bh + row_r + 512 + col) = make_uint2(hi_[0] ^ 0x80008000u, hi_[1] ^ 0x80008000u);
    *(uint2*)(Bh + row_i + col)       = make_uint2(hi_[0], hi_[1]);
    *(uint2*)(Bh + row_i + 512 + col) = make_uint2(hr[0], hr[1]);
}

// ---------------- mma.sync GEMM: 1 pass per stage, buffer 32KB {Ah@0, Bh@16K} ----------------
__device__ __forceinline__ void prefetch_chunk(
    const half* __restrict__ Ah, const half* __restrict__ Bh,
    int arow, int brow, int kb, uint32_t sdst, int tid) {
    const half* srcs[2] = { Ah, Bh };
    const int rows0[2] = { arow, brow };
    #pragma unroll
    for (int arr = 0; arr < 2; ++arr) {
        #pragma unroll
        for (int i = 0; i < 4; ++i) {
            int u = tid + 256 * i, row = u >> 3, seg = u & 7;
            const half* g = srcs[arr] + (size_t)(rows0[arr] + row) * 1024 + kb + seg * 8;
            uint32_t s = sdst + arr * 16384 + SWZ(row * 128 + seg * 16);
            CP_ASYNC16(s, g);
        }
    }
    CP_COMMIT();
}

template<int STAGE>
__global__ void __launch_bounds__(256, 2) k_mma(float* __restrict__ gout,
                                                const float* __restrict__ td,
                                                const float* __restrict__ rd) {
    extern __shared__ __align__(1024) char smem[];
    const int tid = threadIdx.x, wid = tid >> 5, lane = tid & 31;
    const int wm = wid >> 1, wn = wid & 1;
    const int b = blockIdx.z, My = blockIdx.y, Nx = blockIdx.x;
    const half *Ah, *Bh;
    if (STAGE == 0) { Ah = g_A0h;    Bh = g_B0h[b]; }
    else            { Ah = g_A1h[b]; Bh = g_B1h; }
    const int arow = My * 128, brow = Nx * 128;
    const uint32_t sb = smem_u32(smem);

    float c[2][8][4];
    #pragma unroll
    for (int mt = 0; mt < 2; ++mt)
        #pragma unroll
        for (int nt = 0; nt < 8; ++nt)
            #pragma unroll
            for (int q = 0; q < 4; ++q) c[mt][nt][q] = 0.f;

    prefetch_chunk(Ah, Bh, arow, brow, 0, sb, tid);

    for (int ch = 0; ch < 16; ++ch) {
        const uint32_t sbuf = sb + (ch & 1) * 32768;
        if (ch + 1 < 16) {
            prefetch_chunk(Ah, Bh, arow, brow, (ch + 1) * 64,
                           sb + ((ch + 1) & 1) * 32768, tid);
            CP_WAIT(1);
        } else {
            CP_WAIT(0);
        }
        __syncthreads();

        const uint32_t sA = sbuf, sB = sbuf + 16384;
        #pragma unroll
        for (int ks = 0; ks < 4; ++ks) {
            uint32_t ah[2][4], bh[8][2];
            #pragma unroll
            for (int mt = 0; mt < 2; ++mt) {
                int row = wm * 32 + mt * 16 + (lane & 15);
                uint32_t off = SWZ(row * 128 + ks * 32 + (lane >> 4) * 16);
                LDSM_X4(ah[mt][0], ah[mt][1], ah[mt][2], ah[mt][3], sA + off);
            }
            #pragma unroll
            for (int ntp = 0; ntp < 4; ++ntp) {
                int row = wn * 64 + ntp * 16 + (lane >> 4) * 8 + (lane & 7);
                uint32_t off = SWZ(row * 128 + ks * 32 + ((lane >> 3) & 1) * 16);
                LDSM_X4(bh[2 * ntp][0], bh[2 * ntp][1], bh[2 * ntp + 1][0], bh[2 * ntp + 1][1], sB + off);
            }
            #pragma unroll
            for (int mt = 0; mt < 2; ++mt)
                #pragma unroll
                for (int nt = 0; nt < 8; ++nt)
                    MMA16816(c[mt][nt], ah[mt], bh[nt]);
        }
        __syncthreads();
    }

    // ---------------- epilogue ----------------
    const int r0 = My * 128 + wm * 32 + (lane >> 2);
    if (STAGE == 0) {
        half* dh = g_A1h[b];
        #pragma unroll
        for (int mt = 0; mt < 2; ++mt)
            #pragma unroll
            for (int nt = 0; nt < 8; ++nt) {
                int row = r0 + mt * 16;
                int col = Nx * 128 + wn * 64 + nt * 8 + 2 * (lane & 3);
                *(uint32_t*)(dh + (size_t)row * 1024 + col)       = h2_rn(c[mt][nt][0], c[mt][nt][1]);
                *(uint32_t*)(dh + (size_t)(row + 8) * 1024 + col) = h2_rn(c[mt][nt][2], c[mt][nt][3]);
            }
    } else {
        float A_ = 0.f, B_ = 0.f, K_ = 0.f;
        #pragma unroll
        for (int cc = 0; cc < 16; ++cc) {
            float rr = rd[2 * cc], ri = rd[2 * cc + 1];
            float tr = td[2 * cc], ti = td[2 * cc + 1];
            A_ += ri; B_ -= rr; K_ += ti * ri - tr * rr;
        }
        float* O = gout + b * PL;
        #pragma unroll
        for (int mt = 0; mt < 2; ++mt)
            #pragma unroll
            for (int nt = 0; nt < 8; ++nt) {
                int row = r0 + mt * 16;
                int np = Nx * 64 + wn * 32 + nt * 4 + (lane & 3);
                O[(size_t)row * 512 + np] =
                    fmaf(c[mt][nt][1], A_, fmaf(c[mt][nt][0], B_, K_));
                O[(size_t)(row + 8) * 512 + np] =
                    fmaf(c[mt][nt][3], A_, fmaf(c[mt][nt][2], B_, K_));
            }
    }
}

// ---------------- launch ----------------
extern "C" void kernel_launch(void* const* d_in, const int* in_sizes, int n_in,
                              void* d_out, int out_size) {
    (void)in_sizes; (void)n_in; (void)out_size;
    const float* x   = (const float*)d_in[0];
    const float* Wi  = (const float*)d_in[1];
    const float* Wj  = (const float*)d_in[2];
    const float* Wb  = (const float*)d_in[3];
    const float* td  = (const float*)d_in[6];
    const float* rd  = (const float*)d_in[7];
    const float* mi  = (const float*)d_in[8];
    const float* mj  = (const float*)d_in[9];
    const float* inv = (const float*)d_in[10];
    const float* mt  = (const float*)d_in[11];
    float* out = (float*)d_out;

    const int SMEM_G = 2 * 32768;      // 64 KB GEMM, 2 CTAs/SM
    const int SMEM_MOD = 16896 * 4;    // 67.6 KB for k_mod
    cudaFuncSetAttribute(k_mma<0>, cudaFuncAttributeMaxDynamicSharedMemorySize, SMEM_G);
    cudaFuncSetAttribute(k_mma<1>, cudaFuncAttributeMaxDynamicSharedMemorySize, SMEM_G);
    cudaFuncSetAttribute(k_mod, cudaFuncAttributeMaxDynamicSharedMemorySize, SMEM_MOD);

    k_prep<<<640, 256>>>(x, mt, mi, mj, inv, Wi, Wj);
    k_mod<<<256, 256, SMEM_MOD>>>();
    k_packB0<<<dim3(16, 16, 8), 256>>>(Wb);
    dim3 grid(8, 4, 8);
    k_mma<0><<<grid, 256, SMEM_G>>>(nullptr, nullptr, nullptr);
    k_mma<1><<<grid, 256, SMEM_G>>>(out, td, rd);
}

// round 17
// speedup vs baseline: 2.1478x; 1.1060x over previous
#include <cuda_runtime.h>
#include <cuda_fp16.h>
#include <cstdint>

#define PL (512*512)
typedef unsigned long long u64;

// ---------------- scratch ----------------
__device__ float g_part[8][32][2];
__device__ float g_mi[8][2][16][512];
__device__ float g_mj[8][2][16][512];
__device__ uint32_t g_modh[8][PL];       // mod packed half2 (lo=re, hi=im)
__device__ half g_A0h[512 * 1024];       // Wi^T pack (hi only): [m'][k2 = m | 512+m]
__device__ half g_B0h[8][1024 * 1024];   // wd0 block matrix (hi only)
__device__ half g_A1h[8][512 * 1024];    // stage-0 out (hi only): [m'][k2' = n | 512+n]
__device__ half g_B1h[512 * 1024];       // FOLDED Wj: row n' -> [B*Wjr+A*Wji | A*Wjr-B*Wji]

#define SWZ(x) ((x) ^ (((x) >> 3) & 0x70))

__device__ __forceinline__ uint32_t smem_u32(const void* p) {
    uint32_t a;
    asm("{ .reg .u64 t; cvta.to.shared.u64 t, %1; cvt.u32.u64 %0, t; }" : "=r"(a) : "l"(p));
    return a;
}
__device__ __forceinline__ uint32_t h2_rn(float v0, float v1) {
    __half2 h = __floats2half2_rn(v0, v1);
    return *(uint32_t*)&h;
}
#define LDSM_X4(r0, r1, r2, r3, a) \
    asm volatile("ldmatrix.sync.aligned.m8n8.x4.shared.b16 {%0,%1,%2,%3}, [%4];" \
        : "=r"(r0), "=r"(r1), "=r"(r2), "=r"(r3) : "r"(a))
#define MMA16816(c, a, b) \
    asm volatile("mma.sync.aligned.m16n8k16.row.col.f32.f16.f16.f32 " \
        "{%0,%1,%2,%3}, {%4,%5,%6,%7}, {%8,%9}, {%0,%1,%2,%3};" \
        : "+f"((c)[0]), "+f"((c)[1]), "+f"((c)[2]), "+f"((c)[3]) \
        : "r"((a)[0]), "r"((a)[1]), "r"((a)[2]), "r"((a)[3]), "r"((b)[0]), "r"((b)[1]))
#define CP_ASYNC16(s, g) \
    asm volatile("cp.async.cg.shared.global [%0], [%1], 16;" :: "r"(s), "l"(g) : "memory")
#define CP_COMMIT()  asm volatile("cp.async.commit_group;" ::: "memory")
#define CP_WAIT(n)   asm volatile("cp.async.wait_group %0;" :: "n"(n) : "memory")

// ---------------- k_prep: fused mimj (128 blk) + packA0 (256 blk) + packB1' (256 blk) ----------------
__global__ void k_prep(const float* __restrict__ x,  const float* __restrict__ mt,
                       const float* __restrict__ mod_i, const float* __restrict__ mod_j,
                       const float* __restrict__ inv,
                       const float* __restrict__ Wi, const float* __restrict__ Wj,
                       const float* __restrict__ td, const float* __restrict__ rd) {
    __shared__ float sr[32][33], si[32][33];
    const int blk = blockIdx.x, tid = threadIdx.x;

    if (blk < 128) {
        float* st  = &sr[0][0];    // [16][8]
        float* siv = &si[0][0];    // [16][2]
        const int b = blk >> 4, r = blk & 15;
        if (tid < 128) {
            int e = tid & 1, c2 = (tid >> 1) & 15, k = (tid >> 5) & 3;
            float s = 0.f;
            #pragma unroll
            for (int c = 0; c < 16; ++c)
                s += x[b * 16 + c] * mt[(k * 16 + c) * 32 + c2 * 2 + e];
            st[c2 * 8 + k * 2 + e] = s;
        } else if (tid < 160) {
            int q = tid - 128;
            siv[q] = inv[q];
        }
        __syncthreads();
        #pragma unroll
        for (int mm = 0; mm < 2; ++mm) {
            const int m = tid + mm * 256;
            float sir = 0.f, sii = 0.f, sjr = 0.f, sji = 0.f;
            #pragma unroll 4
            for (int c = 0; c < 16; ++c) {
                float t0r = st[c * 8 + 0], t0i = st[c * 8 + 1];
                float t1r = st[c * 8 + 2], t1i = st[c * 8 + 3];
                float t2r = st[c * 8 + 4], t2i = st[c * 8 + 5];
                float t3r = st[c * 8 + 6], t3i = st[c * 8 + 7];
                float ivr = siv[c * 2], ivi = siv[c * 2 + 1];
                float2 vi = ((const float2*)mod_i)[(c * 16 + r) * 512 + m];
                float ar = vi.x + t0r, ai = vi.y + t0i;
                float r1 = ai * t1i - ar * t1r;
                float i1 = ar * t1i + ai * t1r;
                sir += i1 * ivi - r1 * ivr;
                sii += r1 * ivi + i1 * ivr;
                float2 vj = ((const float2*)mod_j)[(c * 16 + r) * 512 + m];
                float br2 = vj.x + t2r, bi2 = vj.y + t2i;
                float r2 = bi2 * t3i - br2 * t3r;
                float i2 = br2 * t3i + bi2 * t3r;
                float idn = 1.f / (r2 * r2 + i2 * i2);
                sjr += (ivr * r2 + ivi * i2) * idn;
                sji += (ivr * i2 - ivi * r2) * idn;
            }
            g_mi[b][0][r][m] = sir; g_mi[b][1][r][m] = sii;
            g_mj[b][0][r][m] = sjr; g_mj[b][1][r][m] = sji;
        }
        return;
    }

    if (blk < 384) {
        // ---- packA0: Wi -> [Wir^T | Wii^T] ----
        const int idx = blk - 128;
        const int mtile = (idx & 15) * 32, pt = (idx >> 4) * 32;
        #pragma unroll
        for (int rr = 0; rr < 4; ++rr) {
            int e = tid + 256 * rr, ml = e >> 5, pl = e & 31;
            float2 v = ((const float2*)Wi)[(mtile + ml) * 512 + pt + pl];
            sr[ml][pl] = v.x; si[ml][pl] = v.y;
        }
        __syncthreads();
        int pl = tid >> 3, m4 = (tid & 7) * 4;
        uint32_t hr[2], hi_[2];
        #pragma unroll
        for (int g = 0; g < 2; ++g) {
            hr[g]  = h2_rn(sr[m4 + 2 * g][pl], sr[m4 + 2 * g + 1][pl]);
            hi_[g] = h2_rn(si[m4 + 2 * g][pl], si[m4 + 2 * g + 1][pl]);
        }
        size_t row = (size_t)(pt + pl) * 1024;
        int col = mtile + m4;
        *(uint2*)(g_A0h + row + col)       = make_uint2(hr[0], hr[1]);
        *(uint2*)(g_A0h + row + 512 + col) = make_uint2(hi_[0], hi_[1]);
        return;
    }

    // ---- packB1': row n' -> [B_*Wjr + A_*Wji | A_*Wjr - B_*Wji] ----
    {
        float A_ = 0.f, B_ = 0.f;
        #pragma unroll
        for (int cc = 0; cc < 16; ++cc) { A_ += rd[2 * cc + 1]; B_ -= rd[2 * cc]; }
        const int idx = blk - 384;
        const int nt = (idx & 15) * 32, pt = (idx >> 4) * 32;
        #pragma unroll
        for (int rr = 0; rr < 4; ++rr) {
            int e = tid + 256 * rr, nl = e >> 5, pl = e & 31;
            float2 v = ((const float2*)Wj)[(nt + nl) * 512 + pt + pl];
            sr[nl][pl] = v.x; si[nl][pl] = v.y;
        }
        __syncthreads();
        int pl = tid >> 3, m4 = (tid & 7) * 4;
        uint32_t c0[2], c1[2];
        #pragma unroll
        for (int g = 0; g < 2; ++g) {
            int a = m4 + 2 * g, bidx = a + 1;
            c0[g] = h2_rn(B_ * sr[a][pl] + A_ * si[a][pl],
                          B_ * sr[bidx][pl] + A_ * si[bidx][pl]);
            c1[g] = h2_rn(A_ * sr[a][pl] - B_ * si[a][pl],
                          A_ * sr[bidx][pl] - B_ * si[bidx][pl]);
        }
        int np = pt + pl;
        size_t row = (size_t)np * 1024;
        int col = nt + m4;
        *(uint2*)(g_B1h + row + col)       = make_uint2(c0[0], c0[1]);
        *(uint2*)(g_B1h + row + 512 + col) = make_uint2(c1[0], c1[1]);
    }
}

// ---------------- k_mod: per (b, 16-m tile); mj cached in smem; writes mod as half2 ----------------
__global__ void k_mod() {
    extern __shared__ float sm[];
    float* smj = sm;            // [r][n][2]
    float* smi = sm + 16384;    // [r][ml][2]
    const int blk = blockIdx.x, b = blk >> 5, mt0 = (blk & 31) * 16;
    const int tid = threadIdx.x;
    const float* mjb = (const float*)g_mj[b];
    for (int i = tid; i < 8192; i += 256) {
        float re = mjb[i], im = mjb[8192 + i];
        smj[2 * i] = re; smj[2 * i + 1] = im;
    }
    if (tid < 256) {
        int r = tid >> 4, ml = tid & 15;
        smi[2 * tid]     = g_mi[b][0][r][mt0 + ml];
        smi[2 * tid + 1] = g_mi[b][1][r][mt0 + ml];
    }
    __syncthreads();

    float s1 = 0.f, s2 = 0.f;
    #pragma unroll
    for (int hh = 0; hh < 2; ++hh) {
        const int n = hh * 256 + tid;
        float cr[16], ci[16];
        #pragma unroll
        for (int ml = 0; ml < 16; ++ml) { cr[ml] = 0.f; ci[ml] = 0.f; }
        #pragma unroll
        for (int r = 0; r < 16; ++r) {
            float2 bj = *(const float2*)&smj[(r * 512 + n) * 2];
            const float4* ai4 = (const float4*)&smi[r * 32];
            #pragma unroll
            for (int mp = 0; mp < 8; ++mp) {
                float4 a2 = ai4[mp];
                cr[2 * mp]     += a2.x * bj.x - a2.y * bj.y;
                ci[2 * mp]     += a2.x * bj.y + a2.y * bj.x;
                cr[2 * mp + 1] += a2.z * bj.x - a2.w * bj.y;
                ci[2 * mp + 1] += a2.z * bj.y + a2.w * bj.x;
            }
        }
        #pragma unroll
        for (int ml = 0; ml < 16; ++ml) {
            g_modh[b][(mt0 + ml) * 512 + n] = h2_rn(cr[ml], ci[ml]);
            s1 += cr[ml]; s2 += cr[ml] * cr[ml];
        }
    }
    __shared__ float rs1[256], rs2[256];
    rs1[tid] = s1; rs2[tid] = s2; __syncthreads();
    for (int off = 128; off; off >>= 1) {
        if (tid < off) { rs1[tid] += rs1[tid + off]; rs2[tid] += rs2[tid + off]; }
        __syncthreads();
    }
    if (tid == 0) { g_part[b][blk & 31][0] = rs1[0]; g_part[b][blk & 31][1] = rs2[0]; }
}

// ---------------- k_packB0: inline stats + wd0 -> B0 block matrix (hi only), mod from half2 ----------------
__global__ void k_packB0(const float* __restrict__ wb) {
    int mt = blockIdx.x * 32, nt = blockIdx.y * 32, b = blockIdx.z;
    __shared__ float s_mean, s_istd;
    const int t = threadIdx.x;
    if (t < 32) {
        float s1 = g_part[b][t][0], s2 = g_part[b][t][1];
        #pragma unroll
        for (int off = 16; off; off >>= 1) {
            s1 += __shfl_down_sync(0xffffffffu, s1, off);
            s2 += __shfl_down_sync(0xffffffffu, s2, off);
        }
        if (t == 0) {
            float mean = s1 * (1.f / 262144.f);
            float var = (s2 - s1 * mean) * (1.f / 262143.f);
            s_mean = mean; s_istd = rsqrtf(var);
        }
    }
    __syncthreads();
    const float mean = s_mean, istd = s_istd;
    __shared__ float wr[32][33], wi[32][33];
    #pragma unroll
    for (int rr = 0; rr < 4; ++rr) {
        int e = t + 256 * rr, ml = e >> 5, nl = e & 31;
        int idx = (mt + ml) * 512 + nt + nl;
        float2 w = ((const float2*)wb)[idx];
        __half2 mo = *(const __half2*)&g_modh[b][idx];
        float mr = __half2float(__low2half(mo));
        float mi2 = __half2float(__high2half(mo));
        wr[ml][nl] = w.x * (1.f + (mr - mean) * istd);
        wi[ml][nl] = w.y * (1.f + mi2);
    }
    __syncthreads();
    int nl = t >> 3, m4 = (t & 7) * 4;
    uint32_t hr[2], hi_[2];
    #pragma unroll
    for (int g = 0; g < 2; ++g) {
        hr[g]  = h2_rn(wr[m4 + 2 * g][nl], wr[m4 + 2 * g + 1][nl]);
        hi_[g] = h2_rn(wi[m4 + 2 * g][nl], wi[m4 + 2 * g + 1][nl]);
    }
    size_t row_r = (size_t)(nt + nl) * 1024;
    size_t row_i = (size_t)(512 + nt + nl) * 1024;
    int col = mt + m4;
    half* Bh = g_B0h[b];
    *(uint2*)(Bh + row_r + col)       = make_uint2(hr[0], hr[1]);
    *(uint2*)(Bh + row_r + 512 + col) = make_uint2(hi_[0] ^ 0x80008000u, hi_[1] ^ 0x80008000u);
    *(uint2*)(Bh + row_i + col)       = make_uint2(hi_[0], hi_[1]);
    *(uint2*)(Bh + row_i + 512 + col) = make_uint2(hr[0], hr[1]);
}

// ---------------- mma.sync GEMM: 1 pass per stage, buffer 32KB {Ah@0, Bh@16K} ----------------
__device__ __forceinline__ void prefetch_chunk(
    const half* __restrict__ Ah, const half* __restrict__ Bh,
    int arow, int brow, int kb, uint32_t sdst, int tid) {
    const half* srcs[2] = { Ah, Bh };
    const int rows0[2] = { arow, brow };
    #pragma unroll
    for (int arr = 0; arr < 2; ++arr) {
        #pragma unroll
        for (int i = 0; i < 4; ++i) {
            int u = tid + 256 * i, row = u >> 3, seg = u & 7;
            const half* g = srcs[arr] + (size_t)(rows0[arr] + row) * 1024 + kb + seg * 8;
            uint32_t s = sdst + arr * 16384 + SWZ(row * 128 + seg * 16);
            CP_ASYNC16(s, g);
        }
    }
    CP_COMMIT();
}

template<int STAGE>
__global__ void __launch_bounds__(256, 2) k_mma(float* __restrict__ gout,
                                                const float* __restrict__ td,
                                                const float* __restrict__ rd) {
    extern __shared__ __align__(1024) char smem[];
    const int tid = threadIdx.x, wid = tid >> 5, lane = tid & 31;
    const int wm = wid >> 1, wn = wid & 1;
    const int b = blockIdx.z, My = blockIdx.y, Nx = blockIdx.x;
    const half *Ah, *Bh;
    if (STAGE == 0) { Ah = g_A0h;    Bh = g_B0h[b]; }
    else            { Ah = g_A1h[b]; Bh = g_B1h; }
    const int arow = My * 128, brow = Nx * 128;
    const uint32_t sb = smem_u32(smem);

    float c[2][8][4];
    #pragma unroll
    for (int mt = 0; mt < 2; ++mt)
        #pragma unroll
        for (int nt = 0; nt < 8; ++nt)
            #pragma unroll
            for (int q = 0; q < 4; ++q) c[mt][nt][q] = 0.f;

    prefetch_chunk(Ah, Bh, arow, brow, 0, sb, tid);

    for (int ch = 0; ch < 16; ++ch) {
        const uint32_t sbuf = sb + (ch & 1) * 32768;
        if (ch + 1 < 16) {
            prefetch_chunk(Ah, Bh, arow, brow, (ch + 1) * 64,
                           sb + ((ch + 1) & 1) * 32768, tid);
            CP_WAIT(1);
        } else {
            CP_WAIT(0);
        }
        __syncthreads();

        const uint32_t sA = sbuf, sB = sbuf + 16384;
        #pragma unroll
        for (int ks = 0; ks < 4; ++ks) {
            uint32_t ah[2][4], bh[8][2];
            #pragma unroll
            for (int mt = 0; mt < 2; ++mt) {
                int row = wm * 32 + mt * 16 + (lane & 15);
                uint32_t off = SWZ(row * 128 + ks * 32 + (lane >> 4) * 16);
                LDSM_X4(ah[mt][0], ah[mt][1], ah[mt][2], ah[mt][3], sA + off);
            }
            #pragma unroll
            for (int ntp = 0; ntp < 4; ++ntp) {
                int row = wn * 64 + ntp * 16 + (lane >> 4) * 8 + (lane & 7);
                uint32_t off = SWZ(row * 128 + ks * 32 + ((lane >> 3) & 1) * 16);
                LDSM_X4(bh[2 * ntp][0], bh[2 * ntp][1], bh[2 * ntp + 1][0], bh[2 * ntp + 1][1], sB + off);
            }
            #pragma unroll
            for (int mt = 0; mt < 2; ++mt)
                #pragma unroll
                for (int nt = 0; nt < 8; ++nt)
                    MMA16816(c[mt][nt], ah[mt], bh[nt]);
        }
        __syncthreads();
    }

    // ---------------- epilogue ----------------
    const int r0 = My * 128 + wm * 32 + (lane >> 2);
    if (STAGE == 0) {
        half* dh = g_A1h[b];
        #pragma unroll
        for (int mt = 0; mt < 2; ++mt)
            #pragma unroll
            for (int nt = 0; nt < 8; ++nt) {
                int row = r0 + mt * 16;
                int col = Nx * 128 + wn * 64 + nt * 8 + 2 * (lane & 3);
                *(uint32_t*)(dh + (size_t)row * 1024 + col)       = h2_rn(c[mt][nt][0], c[mt][nt][1]);
                *(uint32_t*)(dh + (size_t)(row + 8) * 1024 + col) = h2_rn(c[mt][nt][2], c[mt][nt][3]);
            }
    } else {
        float K_ = 0.f;
        #pragma unroll
        for (int cc = 0; cc < 16; ++cc)
            K_ += td[2 * cc + 1] * rd[2 * cc + 1] - td[2 * cc] * rd[2 * cc];
        float* O = gout + b * PL;
        #pragma unroll
        for (int mt = 0; mt < 2; ++mt)
            #pragma unroll
            for (int nt = 0; nt < 8; ++nt) {
                int row = r0 + mt * 16;
                int np = Nx * 128 + wn * 64 + nt * 8 + 2 * (lane & 3);
                *(float2*)&O[(size_t)row * 512 + np] =
                    make_float2(c[mt][nt][0] + K_, c[mt][nt][1] + K_);
                *(float2*)&O[(size_t)(row + 8) * 512 + np] =
                    make_float2(c[mt][nt][2] + K_, c[mt][nt][3] + K_);
            }
    }
}

// ---------------- launch ----------------
extern "C" void kernel_launch(void* const* d_in, const int* in_sizes, int n_in,
                              void* d_out, int out_size) {
    (void)in_sizes; (void)n_in; (void)out_size;
    const float* x   = (const float*)d_in[0];
    const float* Wi  = (const float*)d_in[1];
    const float* Wj  = (const float*)d_in[2];
    const float* Wb  = (const float*)d_in[3];
    const float* td  = (const float*)d_in[6];
    const float* rd  = (const float*)d_in[7];
    const float* mi  = (const float*)d_in[8];
    const float* mj  = (const float*)d_in[9];
    const float* inv = (const float*)d_in[10];
    const float* mt  = (const float*)d_in[11];
    float* out = (float*)d_out;

    const int SMEM_G = 2 * 32768;      // 64 KB GEMM, 2 CTAs/SM
    const int SMEM_MOD = 16896 * 4;    // 67.6 KB for k_mod
    cudaFuncSetAttribute(k_mma<0>, cudaFuncAttributeMaxDynamicSharedMemorySize, SMEM_G);
    cudaFuncSetAttribute(k_mma<1>, cudaFuncAttributeMaxDynamicSharedMemorySize, SMEM_G);
    cudaFuncSetAttribute(k_mod, cudaFuncAttributeMaxDynamicSharedMemorySize, SMEM_MOD);

    k_prep<<<640, 256>>>(x, mt, mi, mj, inv, Wi, Wj, td, rd);
    k_mod<<<256, 256, SMEM_MOD>>>();
    k_packB0<<<dim3(16, 16, 8), 256>>>(Wb);
    k_mma<0><<<dim3(8, 4, 8), 256, SMEM_G>>>(nullptr, nullptr, nullptr);
    k_mma<1><<<dim3(4, 4, 8), 256, SMEM_G>>>(out, td, rd);
}